// round 1
// baseline (speedup 1.0000x reference)
#include <cuda_runtime.h>
#include <cuda_bf16.h>

// ---------------------------------------------------------------------------
// ConvAutoencoder: masked 3D conv autoencoder, fused into 3 kernels.
//   Inputs (metadata order): x(f32 2*128^3), W1(432), W2(1728), Wt1(512),
//                            Wt2(128), occ(i32 2*128^3)
//   Output: f32 2*128^3
//
// K1: conv3x3x3(1->16) + relu + mask(m0) + maxpool2 + m1    (warp per pooled voxel)
// K2: conv3x3x3(16->4) + relu + mask(m1) at 64^3            (warp per voxel)
// K3: maxpool2 + m2 + tconv2(4->16)+relu+mask + tconv2(16->1)+sigmoid+mask
//     (thread per 32^3 voxel -> 4x4x4 output region)
//
// conv_transpose (transpose_kernel=False, VALID, stride 2, k=2):
//   out[2i+d] = W[1-d] * in[i] per spatial dim (kernel index is flipped).
// ---------------------------------------------------------------------------

#define FULLMASK 0xffffffffu

// Intermediate buffers (static device globals; allocation is forbidden)
__device__ float        g_h1p[2 * 64 * 64 * 64 * 16]; // pooled conv1 output (33.5 MB)
__device__ unsigned char g_m1[2 * 64 * 64 * 64];      // pooled mask m1
__device__ float        g_c2 [2 * 64 * 64 * 64 * 4];  // relu(conv2)*m1 at 64^3 (8.4 MB)

// ===========================================================================
// K1: warp per pooled voxel. lane = (child[0..7] << 2) | channel_group[0..3]
// Each lane accumulates 4 channels over 27 taps for its child; max-reduce
// across the 8 children via shfl. Early-out when all 8 children are masked
// (P = 0.9^8 = 0.43 of warps).
// ===========================================================================
__global__ void __launch_bounds__(256) k1_conv_pool(
    const float* __restrict__ x, const int* __restrict__ occ,
    const float* __restrict__ W1)
{
    __shared__ float4 sW1[27 * 4];          // [tap][cgroup] = channels 4cg..4cg+3
    if (threadIdx.x < 108) sW1[threadIdx.x] = ((const float4*)W1)[threadIdx.x];
    __syncthreads();

    const int warp = threadIdx.x >> 5, lane = threadIdx.x & 31;
    const int idx  = blockIdx.x * 8 + warp;           // pooled voxel, 2*64^3 total
    const int px = idx & 63, py = (idx >> 6) & 63, pz = (idx >> 12) & 63, b = idx >> 18;

    const int child = lane >> 2, cg = lane & 3;
    const int cz = 2 * pz + (child >> 2);
    const int cy = 2 * py + ((child >> 1) & 1);
    const int cx = 2 * px + (child & 1);
    const int cidx = ((b * 128 + cz) * 128 + cy) * 128 + cx;
    const int m0c = (occ[cidx] == 0);

    if (__ballot_sync(FULLMASK, m0c) == 0u) {
        if (lane < 4) ((float4*)g_h1p)[idx * 4 + lane] = make_float4(0.f, 0.f, 0.f, 0.f);
        if (lane == 0) g_m1[idx] = 0;
        return;
    }

    float4 acc = make_float4(0.f, 0.f, 0.f, 0.f);
    if (m0c) {
        #pragma unroll
        for (int kz = 0; kz < 3; kz++) {
            const int iz = cz + kz - 1;
            const bool zok = (unsigned)iz < 128u;
            #pragma unroll
            for (int ky = 0; ky < 3; ky++) {
                const int iy = cy + ky - 1;
                const bool yok = zok && ((unsigned)iy < 128u);
                #pragma unroll
                for (int kx = 0; kx < 3; kx++) {
                    const int ix = cx + kx - 1;
                    float v = 0.f;
                    if (yok && ((unsigned)ix < 128u)) {
                        const int i = ((b * 128 + iz) * 128 + iy) * 128 + ix;
                        v = (occ[i] == 0) ? x[i] : 0.f;  // xm = x * m0
                    }
                    const float4 w = sW1[(kz * 9 + ky * 3 + kx) * 4 + cg];
                    acc.x = fmaf(v, w.x, acc.x);
                    acc.y = fmaf(v, w.y, acc.y);
                    acc.z = fmaf(v, w.z, acc.z);
                    acc.w = fmaf(v, w.w, acc.w);
                }
            }
        }
        acc.x = fmaxf(acc.x, 0.f); acc.y = fmaxf(acc.y, 0.f);
        acc.z = fmaxf(acc.z, 0.f); acc.w = fmaxf(acc.w, 0.f);
    }
    // max over the 8 children (lanes sharing cg are 4 apart)
    #pragma unroll
    for (int m = 4; m <= 16; m <<= 1) {
        acc.x = fmaxf(acc.x, __shfl_xor_sync(FULLMASK, acc.x, m));
        acc.y = fmaxf(acc.y, __shfl_xor_sync(FULLMASK, acc.y, m));
        acc.z = fmaxf(acc.z, __shfl_xor_sync(FULLMASK, acc.z, m));
        acc.w = fmaxf(acc.w, __shfl_xor_sync(FULLMASK, acc.w, m));
    }
    if (lane < 4) ((float4*)g_h1p)[idx * 4 + lane] = acc;   // NDHWC, 16 ch
    if (lane == 0) g_m1[idx] = 1;
}

// ===========================================================================
// K2: warp per 64^3 voxel. lane = (co_pair[0..1] << 4) | ci[0..15].
// Each lane accumulates 2 output channels for its input channel over 27 taps,
// then sum-reduce over the 16 ci lanes. Early-out when m1 == 0 (43% of warps).
// ===========================================================================
__global__ void __launch_bounds__(256) k2_conv(const float* __restrict__ W2)
{
    __shared__ float sW2[27 * 16 * 4];
    for (int i = threadIdx.x; i < 1728; i += 256) sW2[i] = W2[i];
    __syncthreads();

    const int warp = threadIdx.x >> 5, lane = threadIdx.x & 31;
    const int idx  = blockIdx.x * 8 + warp;           // 64^3 voxel, 2*64^3 total
    const int vx = idx & 63, vy = (idx >> 6) & 63, vz = (idx >> 12) & 63, b = idx >> 18;

    if (g_m1[idx] == 0) {
        if (lane == 0) ((float4*)g_c2)[idx] = make_float4(0.f, 0.f, 0.f, 0.f);
        return;
    }

    const int ci = lane & 15, cop = lane >> 4;
    float a0 = 0.f, a1 = 0.f;
    #pragma unroll
    for (int kz = 0; kz < 3; kz++) {
        const int iz = vz + kz - 1;
        const bool zok = (unsigned)iz < 64u;
        #pragma unroll
        for (int ky = 0; ky < 3; ky++) {
            const int iy = vy + ky - 1;
            const bool yok = zok && ((unsigned)iy < 64u);
            #pragma unroll
            for (int kx = 0; kx < 3; kx++) {
                const int ix = vx + kx - 1;
                if (yok && ((unsigned)ix < 64u)) {
                    const int n = ((b * 64 + iz) * 64 + iy) * 64 + ix;
                    const float v = g_h1p[n * 16 + ci];
                    const float* w = &sW2[((kz * 9 + ky * 3 + kx) * 16 + ci) * 4 + cop * 2];
                    a0 = fmaf(v, w[0], a0);
                    a1 = fmaf(v, w[1], a1);
                }
            }
        }
    }
    #pragma unroll
    for (int m = 1; m <= 8; m <<= 1) {
        a0 += __shfl_xor_sync(FULLMASK, a0, m);
        a1 += __shfl_xor_sync(FULLMASK, a1, m);
    }
    if (ci == 0) {   // lanes 0 (co 0,1) and 16 (co 2,3)
        float2 r;
        r.x = fmaxf(a0, 0.f);
        r.y = fmaxf(a1, 0.f);
        ((float2*)g_c2)[idx * 2 + cop] = r;
    }
}

// ===========================================================================
// K3: thread per 32^3 voxel. Pools its 8 children (conv2 outputs + m1->m2),
// then expands: tconv1(4->16, flipped k) + relu + mask(m3=up(m2)=m2[v]),
// tconv2(16->1, flipped k) + sigmoid + mask(m4=up(m3)=m2[v]).
// Writes the voxel's 4x4x4 output region with float4 rows (coalesced:
// warp spans the full x row).
// ===========================================================================
__global__ void __launch_bounds__(256) k3_tconv(
    const float* __restrict__ Wt1, const float* __restrict__ Wt2,
    float* __restrict__ out)
{
    __shared__ float sWt1[8 * 4 * 16];
    __shared__ float sWt2[8 * 16];
    for (int i = threadIdx.x; i < 512; i += 256) sWt1[i] = Wt1[i];
    if (threadIdx.x < 128) sWt2[threadIdx.x] = Wt2[threadIdx.x];
    __syncthreads();

    const int idx = blockIdx.x * 256 + threadIdx.x;   // 2*32^3 total
    const int vx = idx & 31, vy = (idx >> 5) & 31, vz = (idx >> 10) & 31, b = idx >> 15;

    // pool 8 children (values are relu*mask >= 0, so max with 0-init is exact)
    float4 p = make_float4(0.f, 0.f, 0.f, 0.f);
    int m2 = 0;
    #pragma unroll
    for (int d = 0; d < 8; d++) {
        const int czi = 2 * vz + (d >> 2);
        const int cyi = 2 * vy + ((d >> 1) & 1);
        const int cxi = 2 * vx + (d & 1);
        const int n = ((b * 64 + czi) * 64 + cyi) * 64 + cxi;
        m2 |= g_m1[n];
        const float4 c = ((const float4*)g_c2)[n];
        p.x = fmaxf(p.x, c.x); p.y = fmaxf(p.y, c.y);
        p.z = fmaxf(p.z, c.z); p.w = fmaxf(p.w, c.w);
    }

    const int oz0 = 4 * vz, oy0 = 4 * vy, ox0 = 4 * vx;
    if (!m2) {
        const float4 z = make_float4(0.f, 0.f, 0.f, 0.f);
        #pragma unroll
        for (int dz = 0; dz < 4; dz++)
            #pragma unroll
            for (int dy = 0; dy < 4; dy++) {
                const int o = ((b * 128 + oz0 + dz) * 128 + (oy0 + dy)) * 128 + ox0;
                *(float4*)&out[o] = z;
            }
        return;
    }

    #pragma unroll
    for (int qz = 0; qz < 2; qz++)
    #pragma unroll
    for (int qy = 0; qy < 2; qy++) {
        // tconv1: h3 at the two 64^3 children (qx = 0,1); kernel index flipped
        float h3[2][16];
        #pragma unroll
        for (int qx = 0; qx < 2; qx++) {
            const int base = (((1 - qz) * 2 + (1 - qy)) * 2 + (1 - qx)) * 64;
            #pragma unroll
            for (int c = 0; c < 16; c++) {
                float s = p.x * sWt1[base + c];
                s = fmaf(p.y, sWt1[base + 16 + c], s);
                s = fmaf(p.z, sWt1[base + 32 + c], s);
                s = fmaf(p.w, sWt1[base + 48 + c], s);
                h3[qx][c] = fmaxf(s, 0.f);   // m3 = m2[v] = 1 here
            }
        }
        // tconv2 + sigmoid; 4 outputs per (oz,oy) row -> float4 store
        #pragma unroll
        for (int ez = 0; ez < 2; ez++)
        #pragma unroll
        for (int ey = 0; ey < 2; ey++) {
            const int kz2 = 1 - ez, ky2 = 1 - ey;
            float4 r;
            float* rp = &r.x;
            #pragma unroll
            for (int j = 0; j < 4; j++) {          // ox offset = 2*qx + ex = j
                const int qx = j >> 1, ex = j & 1;
                const float* w = &sWt2[((kz2 * 2 + ky2) * 2 + (1 - ex)) * 16];
                float s = 0.f;
                #pragma unroll
                for (int c = 0; c < 16; c++) s = fmaf(h3[qx][c], w[c], s);
                rp[j] = 1.f / (1.f + __expf(-s));  // m4 = m2[v] = 1 here
            }
            const int oz = oz0 + 2 * qz + ez;
            const int oy = oy0 + 2 * qy + ey;
            const int o = ((b * 128 + oz) * 128 + oy) * 128 + ox0;
            *(float4*)&out[o] = r;
        }
    }
}

// ===========================================================================
extern "C" void kernel_launch(void* const* d_in, const int* in_sizes, int n_in,
                              void* d_out, int out_size)
{
    const float* x   = (const float*)d_in[0];
    const float* W1  = (const float*)d_in[1];
    const float* W2  = (const float*)d_in[2];
    const float* Wt1 = (const float*)d_in[3];
    const float* Wt2 = (const float*)d_in[4];
    const int*   occ = (const int*)d_in[5];
    float* out = (float*)d_out;

    k1_conv_pool<<<65536, 256>>>(x, occ, W1);   // 2*64^3 warps
    k2_conv<<<65536, 256>>>(W2);                // 2*64^3 warps
    k3_tconv<<<256, 256>>>(Wt1, Wt2, out);      // 2*32^3 threads
}

// round 2
// speedup vs baseline: 1.0370x; 1.0370x over previous
#include <cuda_runtime.h>
#include <cuda_bf16.h>

// ---------------------------------------------------------------------------
// ConvAutoencoder, round 2: padded intermediates + cooperative smem slabs.
//
// K0: xm = x * (occ==0) into zero-PADDED 130^3 buffer (no bounds checks later)
// K1: conv3(1->16)+relu+mask+pool -> padded 66^3 h1 buffer. Warp per pooled
//     voxel; 64-float input slab loaded with 2 warp-LDGs, staged in smem.
// K2: conv3(16->4)+relu+mask at 64^3. Warp per voxel; 432-float slab via
//     4 warp-LDG.128s.
// K3: pool + tconv(4->16)+relu+mask + tconv(16->1)+sigmoid+mask (unchanged).
//
// conv_transpose (VALID, stride 2, k=2): out[2i+d] = W[1-d] * in[i] per dim.
// ---------------------------------------------------------------------------

#define FULLMASK 0xffffffffu

#define XP   130                 // padded 128 + 2 halo
#define XP2  (XP * XP)           // 16900
#define HP   66                  // padded 64 + 2 halo
#define HROW (HP * 16)           // 1056 floats per padded h1 row
#define HSLC (HP * HP * 16)      // 69696 floats per padded h1 slice

// Zero-initialized device globals; halo regions are NEVER written -> stay 0.
__device__ float         g_xm  [2 * XP * XP * XP];        // 17.6 MB padded xm
__device__ float         g_h1pp[2 * HP * HP * HP * 16];   // 36.8 MB padded h1
__device__ unsigned char g_m1  [2 * 64 * 64 * 64];        // pooled mask m1
__device__ float         g_c2  [2 * 64 * 64 * 64 * 4];    // relu(conv2)*m1

// ===========================================================================
// K0: masked input into padded buffer.
// ===========================================================================
__global__ void __launch_bounds__(256) k0_xm(
    const float* __restrict__ x, const int* __restrict__ occ)
{
    const int i = blockIdx.x * 256 + threadIdx.x;        // 2*128^3
    const int xx = i & 127, yy = (i >> 7) & 127, zz = (i >> 14) & 127, b = i >> 21;
    const float v = (occ[i] == 0) ? x[i] : 0.f;
    g_xm[((b * XP + zz + 1) * XP + yy + 1) * XP + xx + 1] = v;
}

// ===========================================================================
// K1: warp per pooled voxel. lane = (child[0..7] << 2) | cgroup[0..3].
// 64-float input slab (4x4x4 around the pooled voxel's children) is loaded
// cooperatively (2 LDG per lane) and staged in smem; all 27 taps then read
// smem with compile-time offsets. Early-out when all 8 children masked.
// ===========================================================================
__global__ void __launch_bounds__(256) k1_conv_pool(
    const int* __restrict__ occ, const float* __restrict__ W1)
{
    __shared__ float4 sW1[27 * 4];           // [tap][cg]
    __shared__ float  slab[8][64];           // per-warp 4x4x4 input slab
    if (threadIdx.x < 108) sW1[threadIdx.x] = ((const float4*)W1)[threadIdx.x];
    __syncthreads();

    const int warp = threadIdx.x >> 5, lane = threadIdx.x & 31;
    const int idx  = blockIdx.x * 8 + warp;              // pooled voxel
    const int px = idx & 63, py = (idx >> 6) & 63, pz = (idx >> 12) & 63, b = idx >> 18;

    const int child = lane >> 2, cg = lane & 3;
    const int zc = child >> 2, yc = (child >> 1) & 1, xc = child & 1;
    const int cz = 2 * pz + zc, cy = 2 * py + yc, cx = 2 * px + xc;
    const int m0c = (occ[((b * 128 + cz) * 128 + cy) * 128 + cx] == 0);

    const int h1base = (((b * HP + pz + 1) * HP + py + 1) * HP + px + 1) * 4; // f4 idx
    if (__ballot_sync(FULLMASK, m0c) == 0u) {
        if (lane < 4) ((float4*)g_h1pp)[h1base + lane] = make_float4(0.f, 0.f, 0.f, 0.f);
        if (lane == 0) g_m1[idx] = 0;
        return;
    }

    // cooperative slab load: padded coords (2p-1)+1 = 2p .. 2p+3
    {
        const int sbase = ((b * XP + 2 * pz) * XP + 2 * py) * XP + 2 * px;
        #pragma unroll
        for (int t = 0; t < 2; t++) {
            const int l = lane + t * 32;
            const int sz_ = l >> 4, sy_ = (l >> 2) & 3, sx_ = l & 3;
            slab[warp][l] = g_xm[sbase + sz_ * XP2 + sy_ * XP + sx_];
        }
    }
    __syncwarp();

    const int cbase = zc * 16 + yc * 4 + xc;
    float4 acc = make_float4(0.f, 0.f, 0.f, 0.f);
    #pragma unroll
    for (int kz = 0; kz < 3; kz++)
    #pragma unroll
    for (int ky = 0; ky < 3; ky++)
    #pragma unroll
    for (int kx = 0; kx < 3; kx++) {
        const float  v = slab[warp][cbase + kz * 16 + ky * 4 + kx];
        const float4 w = sW1[(kz * 9 + ky * 3 + kx) * 4 + cg];
        acc.x = fmaf(v, w.x, acc.x);
        acc.y = fmaf(v, w.y, acc.y);
        acc.z = fmaf(v, w.z, acc.z);
        acc.w = fmaf(v, w.w, acc.w);
    }
    const float mf = m0c ? 1.f : 0.f;        // relu + per-child mask
    acc.x = fmaxf(acc.x, 0.f) * mf; acc.y = fmaxf(acc.y, 0.f) * mf;
    acc.z = fmaxf(acc.z, 0.f) * mf; acc.w = fmaxf(acc.w, 0.f) * mf;

    #pragma unroll
    for (int m = 4; m <= 16; m <<= 1) {      // max over 8 children
        acc.x = fmaxf(acc.x, __shfl_xor_sync(FULLMASK, acc.x, m));
        acc.y = fmaxf(acc.y, __shfl_xor_sync(FULLMASK, acc.y, m));
        acc.z = fmaxf(acc.z, __shfl_xor_sync(FULLMASK, acc.z, m));
        acc.w = fmaxf(acc.w, __shfl_xor_sync(FULLMASK, acc.w, m));
    }
    if (lane < 4) ((float4*)g_h1pp)[h1base + lane] = acc;
    if (lane == 0) g_m1[idx] = 1;
}

// ===========================================================================
// K2: warp per 64^3 voxel. lane = (cop[0..1] << 4) | ci[0..15].
// 432-float input slab (3x3x3 voxels x 16 ch) loaded cooperatively as
// float4s (108 per warp), then 27 taps from smem, sum-reduce over ci lanes.
// ===========================================================================
__global__ void __launch_bounds__(256) k2_conv(const float* __restrict__ W2)
{
    __shared__ float  sW2r[27 * 2 * 16 * 2];   // [tap][cop][ci][j]
    __shared__ float4 slab4[8][108];           // per-warp 3x3x3x16 slab
    for (int i = threadIdx.x; i < 1728; i += 256) {
        const int tap = i >> 6, r = i & 63, ci = r >> 2, co = r & 3;
        sW2r[(((tap * 2) + (co >> 1)) * 16 + ci) * 2 + (co & 1)] = W2[i];
    }
    __syncthreads();

    const int warp = threadIdx.x >> 5, lane = threadIdx.x & 31;
    const int idx  = blockIdx.x * 8 + warp;
    const int vx = idx & 63, vy = (idx >> 6) & 63, vz = (idx >> 12) & 63, b = idx >> 18;

    if (g_m1[idx] == 0) {
        if (lane == 0) ((float4*)g_c2)[idx] = make_float4(0.f, 0.f, 0.f, 0.f);
        return;
    }

    // slab load: padded corner (vz-1)+1 = vz, rows of 12 consecutive float4s
    {
        const float4* hp4 = (const float4*)g_h1pp;
        const int base4 = (((b * HP + vz) * HP + vy) * HP + vx) * 4;
        #pragma unroll
        for (int t = 0; t < 4; t++) {
            const int l = lane + t * 32;
            if (l < 108) {
                const int zz = l / 36, r = l % 36, yy = r / 12, q = r % 12;
                slab4[warp][l] = hp4[base4 + zz * (HP * HP * 4) + yy * (HP * 4) + q];
            }
        }
    }
    __syncwarp();

    const int ci = lane & 15, cop = lane >> 4;
    const float* slabf = (const float*)slab4[warp];
    float a0 = 0.f, a1 = 0.f;
    #pragma unroll
    for (int kz = 0; kz < 3; kz++)
    #pragma unroll
    for (int ky = 0; ky < 3; ky++)
    #pragma unroll
    for (int kx = 0; kx < 3; kx++) {
        const int tap = kz * 9 + ky * 3 + kx;
        const float  v = slabf[(kz * 3 + ky) * 48 + kx * 16 + ci];
        const float2 w = *(const float2*)&sW2r[((tap * 2 + cop) * 16 + ci) * 2];
        a0 = fmaf(v, w.x, a0);
        a1 = fmaf(v, w.y, a1);
    }
    #pragma unroll
    for (int m = 1; m <= 8; m <<= 1) {
        a0 += __shfl_xor_sync(FULLMASK, a0, m);
        a1 += __shfl_xor_sync(FULLMASK, a1, m);
    }
    if (ci == 0) {
        float2 r;
        r.x = fmaxf(a0, 0.f);
        r.y = fmaxf(a1, 0.f);
        ((float2*)g_c2)[idx * 2 + cop] = r;
    }
}

// ===========================================================================
// K3: thread per 32^3 voxel: pool + tconv1 + relu + mask + tconv2 + sigmoid.
// ===========================================================================
__global__ void __launch_bounds__(256) k3_tconv(
    const float* __restrict__ Wt1, const float* __restrict__ Wt2,
    float* __restrict__ out)
{
    __shared__ float sWt1[8 * 4 * 16];
    __shared__ float sWt2[8 * 16];
    for (int i = threadIdx.x; i < 512; i += 256) sWt1[i] = Wt1[i];
    if (threadIdx.x < 128) sWt2[threadIdx.x] = Wt2[threadIdx.x];
    __syncthreads();

    const int idx = blockIdx.x * 256 + threadIdx.x;   // 2*32^3
    const int vx = idx & 31, vy = (idx >> 5) & 31, vz = (idx >> 10) & 31, b = idx >> 15;

    float4 p = make_float4(0.f, 0.f, 0.f, 0.f);
    int m2 = 0;
    #pragma unroll
    for (int d = 0; d < 8; d++) {
        const int czi = 2 * vz + (d >> 2);
        const int cyi = 2 * vy + ((d >> 1) & 1);
        const int cxi = 2 * vx + (d & 1);
        const int n = ((b * 64 + czi) * 64 + cyi) * 64 + cxi;
        m2 |= g_m1[n];
        const float4 c = ((const float4*)g_c2)[n];
        p.x = fmaxf(p.x, c.x); p.y = fmaxf(p.y, c.y);
        p.z = fmaxf(p.z, c.z); p.w = fmaxf(p.w, c.w);
    }

    const int oz0 = 4 * vz, oy0 = 4 * vy, ox0 = 4 * vx;
    if (!m2) {
        const float4 z = make_float4(0.f, 0.f, 0.f, 0.f);
        #pragma unroll
        for (int dz = 0; dz < 4; dz++)
            #pragma unroll
            for (int dy = 0; dy < 4; dy++) {
                const int o = ((b * 128 + oz0 + dz) * 128 + (oy0 + dy)) * 128 + ox0;
                *(float4*)&out[o] = z;
            }
        return;
    }

    #pragma unroll
    for (int qz = 0; qz < 2; qz++)
    #pragma unroll
    for (int qy = 0; qy < 2; qy++) {
        float h3[2][16];
        #pragma unroll
        for (int qx = 0; qx < 2; qx++) {
            const int base = (((1 - qz) * 2 + (1 - qy)) * 2 + (1 - qx)) * 64;
            #pragma unroll
            for (int c = 0; c < 16; c++) {
                float s = p.x * sWt1[base + c];
                s = fmaf(p.y, sWt1[base + 16 + c], s);
                s = fmaf(p.z, sWt1[base + 32 + c], s);
                s = fmaf(p.w, sWt1[base + 48 + c], s);
                h3[qx][c] = fmaxf(s, 0.f);
            }
        }
        #pragma unroll
        for (int ez = 0; ez < 2; ez++)
        #pragma unroll
        for (int ey = 0; ey < 2; ey++) {
            const int kz2 = 1 - ez, ky2 = 1 - ey;
            float4 r;
            float* rp = &r.x;
            #pragma unroll
            for (int j = 0; j < 4; j++) {
                const int qx = j >> 1, ex = j & 1;
                const float* w = &sWt2[((kz2 * 2 + ky2) * 2 + (1 - ex)) * 16];
                float s = 0.f;
                #pragma unroll
                for (int c = 0; c < 16; c++) s = fmaf(h3[qx][c], w[c], s);
                rp[j] = 1.f / (1.f + __expf(-s));
            }
            const int oz = oz0 + 2 * qz + ez;
            const int oy = oy0 + 2 * qy + ey;
            const int o = ((b * 128 + oz) * 128 + oy) * 128 + ox0;
            *(float4*)&out[o] = r;
        }
    }
}

// ===========================================================================
extern "C" void kernel_launch(void* const* d_in, const int* in_sizes, int n_in,
                              void* d_out, int out_size)
{
    const float* x   = (const float*)d_in[0];
    const float* W1  = (const float*)d_in[1];
    const float* W2  = (const float*)d_in[2];
    const float* Wt1 = (const float*)d_in[3];
    const float* Wt2 = (const float*)d_in[4];
    const int*   occ = (const int*)d_in[5];
    float* out = (float*)d_out;

    k0_xm       <<<16384, 256>>>(x, occ);       // 2*128^3 threads
    k1_conv_pool<<<65536, 256>>>(occ, W1);      // 2*64^3 warps
    k2_conv     <<<65536, 256>>>(W2);           // 2*64^3 warps
    k3_tconv    <<<256,   256>>>(Wt1, Wt2, out);// 2*32^3 threads
}

// round 3
// speedup vs baseline: 1.0957x; 1.0567x over previous
#include <cuda_runtime.h>
#include <cuda_bf16.h>

// ---------------------------------------------------------------------------
// ConvAutoencoder, round 2: padded intermediates + cooperative smem slabs.
//
// K0: xm = x * (occ==0) into zero-PADDED 130^3 buffer (no bounds checks later)
// K1: conv3(1->16)+relu+mask+pool -> padded 66^3 h1 buffer. Warp per pooled
//     voxel; 64-float input slab loaded with 2 warp-LDGs, staged in smem.
// K2: conv3(16->4)+relu+mask at 64^3. Warp per voxel; 432-float slab via
//     4 warp-LDG.128s.
// K3: pool + tconv(4->16)+relu+mask + tconv(16->1)+sigmoid+mask (unchanged).
//
// conv_transpose (VALID, stride 2, k=2): out[2i+d] = W[1-d] * in[i] per dim.
// ---------------------------------------------------------------------------

#define FULLMASK 0xffffffffu

#define XP   130                 // padded 128 + 2 halo
#define XP2  (XP * XP)           // 16900
#define HP   66                  // padded 64 + 2 halo
#define HROW (HP * 16)           // 1056 floats per padded h1 row
#define HSLC (HP * HP * 16)      // 69696 floats per padded h1 slice

// Zero-initialized device globals; halo regions are NEVER written -> stay 0.
__device__ float         g_xm  [2 * XP * XP * XP];        // 17.6 MB padded xm
__device__ float         g_h1pp[2 * HP * HP * HP * 16];   // 36.8 MB padded h1
__device__ unsigned char g_m1  [2 * 64 * 64 * 64];        // pooled mask m1
__device__ float         g_c2  [2 * 64 * 64 * 64 * 4];    // relu(conv2)*m1

// ===========================================================================
// K0: masked input into padded buffer.
// ===========================================================================
__global__ void __launch_bounds__(256) k0_xm(
    const float* __restrict__ x, const int* __restrict__ occ)
{
    const int i = blockIdx.x * 256 + threadIdx.x;        // 2*128^3
    const int xx = i & 127, yy = (i >> 7) & 127, zz = (i >> 14) & 127, b = i >> 21;
    const float v = (occ[i] == 0) ? x[i] : 0.f;
    g_xm[((b * XP + zz + 1) * XP + yy + 1) * XP + xx + 1] = v;
}

// ===========================================================================
// K1: warp per pooled voxel. lane = (child[0..7] << 2) | cgroup[0..3].
// 64-float input slab (4x4x4 around the pooled voxel's children) is loaded
// cooperatively (2 LDG per lane) and staged in smem; all 27 taps then read
// smem with compile-time offsets. Early-out when all 8 children masked.
// ===========================================================================
__global__ void __launch_bounds__(256) k1_conv_pool(
    const int* __restrict__ occ, const float* __restrict__ W1)
{
    __shared__ float4 sW1[27 * 4];           // [tap][cg]
    __shared__ float  slab[8][64];           // per-warp 4x4x4 input slab
    if (threadIdx.x < 108) sW1[threadIdx.x] = ((const float4*)W1)[threadIdx.x];
    __syncthreads();

    const int warp = threadIdx.x >> 5, lane = threadIdx.x & 31;
    const int idx  = blockIdx.x * 8 + warp;              // pooled voxel
    const int px = idx & 63, py = (idx >> 6) & 63, pz = (idx >> 12) & 63, b = idx >> 18;

    const int child = lane >> 2, cg = lane & 3;
    const int zc = child >> 2, yc = (child >> 1) & 1, xc = child & 1;
    const int cz = 2 * pz + zc, cy = 2 * py + yc, cx = 2 * px + xc;
    const int m0c = (occ[((b * 128 + cz) * 128 + cy) * 128 + cx] == 0);

    const int h1base = (((b * HP + pz + 1) * HP + py + 1) * HP + px + 1) * 4; // f4 idx
    if (__ballot_sync(FULLMASK, m0c) == 0u) {
        if (lane < 4) ((float4*)g_h1pp)[h1base + lane] = make_float4(0.f, 0.f, 0.f, 0.f);
        if (lane == 0) g_m1[idx] = 0;
        return;
    }

    // cooperative slab load: padded coords (2p-1)+1 = 2p .. 2p+3
    {
        const int sbase = ((b * XP + 2 * pz) * XP + 2 * py) * XP + 2 * px;
        #pragma unroll
        for (int t = 0; t < 2; t++) {
            const int l = lane + t * 32;
            const int sz_ = l >> 4, sy_ = (l >> 2) & 3, sx_ = l & 3;
            slab[warp][l] = g_xm[sbase + sz_ * XP2 + sy_ * XP + sx_];
        }
    }
    __syncwarp();

    const int cbase = zc * 16 + yc * 4 + xc;
    float4 acc = make_float4(0.f, 0.f, 0.f, 0.f);
    #pragma unroll
    for (int kz = 0; kz < 3; kz++)
    #pragma unroll
    for (int ky = 0; ky < 3; ky++)
    #pragma unroll
    for (int kx = 0; kx < 3; kx++) {
        const float  v = slab[warp][cbase + kz * 16 + ky * 4 + kx];
        const float4 w = sW1[(kz * 9 + ky * 3 + kx) * 4 + cg];
        acc.x = fmaf(v, w.x, acc.x);
        acc.y = fmaf(v, w.y, acc.y);
        acc.z = fmaf(v, w.z, acc.z);
        acc.w = fmaf(v, w.w, acc.w);
    }
    const float mf = m0c ? 1.f : 0.f;        // relu + per-child mask
    acc.x = fmaxf(acc.x, 0.f) * mf; acc.y = fmaxf(acc.y, 0.f) * mf;
    acc.z = fmaxf(acc.z, 0.f) * mf; acc.w = fmaxf(acc.w, 0.f) * mf;

    #pragma unroll
    for (int m = 4; m <= 16; m <<= 1) {      // max over 8 children
        acc.x = fmaxf(acc.x, __shfl_xor_sync(FULLMASK, acc.x, m));
        acc.y = fmaxf(acc.y, __shfl_xor_sync(FULLMASK, acc.y, m));
        acc.z = fmaxf(acc.z, __shfl_xor_sync(FULLMASK, acc.z, m));
        acc.w = fmaxf(acc.w, __shfl_xor_sync(FULLMASK, acc.w, m));
    }
    if (lane < 4) ((float4*)g_h1pp)[h1base + lane] = acc;
    if (lane == 0) g_m1[idx] = 1;
}

// ===========================================================================
// K2: warp per 64^3 voxel. lane = (cop[0..1] << 4) | ci[0..15].
// 432-float input slab (3x3x3 voxels x 16 ch) loaded cooperatively as
// float4s (108 per warp), then 27 taps from smem, sum-reduce over ci lanes.
// ===========================================================================
__global__ void __launch_bounds__(256) k2_conv(const float* __restrict__ W2)
{
    __shared__ float  sW2r[27 * 2 * 16 * 2];   // [tap][cop][ci][j]
    __shared__ float4 slab4[8][108];           // per-warp 3x3x3x16 slab
    for (int i = threadIdx.x; i < 1728; i += 256) {
        const int tap = i >> 6, r = i & 63, ci = r >> 2, co = r & 3;
        sW2r[(((tap * 2) + (co >> 1)) * 16 + ci) * 2 + (co & 1)] = W2[i];
    }
    __syncthreads();

    const int warp = threadIdx.x >> 5, lane = threadIdx.x & 31;
    const int idx  = blockIdx.x * 8 + warp;
    const int vx = idx & 63, vy = (idx >> 6) & 63, vz = (idx >> 12) & 63, b = idx >> 18;

    if (g_m1[idx] == 0) {
        if (lane == 0) ((float4*)g_c2)[idx] = make_float4(0.f, 0.f, 0.f, 0.f);
        return;
    }

    // slab load: padded corner (vz-1)+1 = vz, rows of 12 consecutive float4s
    {
        const float4* hp4 = (const float4*)g_h1pp;
        const int base4 = (((b * HP + vz) * HP + vy) * HP + vx) * 4;
        #pragma unroll
        for (int t = 0; t < 4; t++) {
            const int l = lane + t * 32;
            if (l < 108) {
                const int zz = l / 36, r = l % 36, yy = r / 12, q = r % 12;
                slab4[warp][l] = hp4[base4 + zz * (HP * HP * 4) + yy * (HP * 4) + q];
            }
        }
    }
    __syncwarp();

    const int ci = lane & 15, cop = lane >> 4;
    const float* slabf = (const float*)slab4[warp];
    float a0 = 0.f, a1 = 0.f;
    #pragma unroll
    for (int kz = 0; kz < 3; kz++)
    #pragma unroll
    for (int ky = 0; ky < 3; ky++)
    #pragma unroll
    for (int kx = 0; kx < 3; kx++) {
        const int tap = kz * 9 + ky * 3 + kx;
        const float  v = slabf[(kz * 3 + ky) * 48 + kx * 16 + ci];
        const float2 w = *(const float2*)&sW2r[((tap * 2 + cop) * 16 + ci) * 2];
        a0 = fmaf(v, w.x, a0);
        a1 = fmaf(v, w.y, a1);
    }
    #pragma unroll
    for (int m = 1; m <= 8; m <<= 1) {
        a0 += __shfl_xor_sync(FULLMASK, a0, m);
        a1 += __shfl_xor_sync(FULLMASK, a1, m);
    }
    if (ci == 0) {
        float2 r;
        r.x = fmaxf(a0, 0.f);
        r.y = fmaxf(a1, 0.f);
        ((float2*)g_c2)[idx * 2 + cop] = r;
    }
}

// ===========================================================================
// K3: thread per 32^3 voxel: pool + tconv1 + relu + mask + tconv2 + sigmoid.
// ===========================================================================
__global__ void __launch_bounds__(256) k3_tconv(
    const float* __restrict__ Wt1, const float* __restrict__ Wt2,
    float* __restrict__ out)
{
    __shared__ float sWt1[8 * 4 * 16];
    __shared__ float sWt2[8 * 16];
    for (int i = threadIdx.x; i < 512; i += 256) sWt1[i] = Wt1[i];
    if (threadIdx.x < 128) sWt2[threadIdx.x] = Wt2[threadIdx.x];
    __syncthreads();

    const int idx = blockIdx.x * 256 + threadIdx.x;   // 2*32^3
    const int vx = idx & 31, vy = (idx >> 5) & 31, vz = (idx >> 10) & 31, b = idx >> 15;

    float4 p = make_float4(0.f, 0.f, 0.f, 0.f);
    int m2 = 0;
    #pragma unroll
    for (int d = 0; d < 8; d++) {
        const int czi = 2 * vz + (d >> 2);
        const int cyi = 2 * vy + ((d >> 1) & 1);
        const int cxi = 2 * vx + (d & 1);
        const int n = ((b * 64 + czi) * 64 + cyi) * 64 + cxi;
        m2 |= g_m1[n];
        const float4 c = ((const float4*)g_c2)[n];
        p.x = fmaxf(p.x, c.x); p.y = fmaxf(p.y, c.y);
        p.z = fmaxf(p.z, c.z); p.w = fmaxf(p.w, c.w);
    }

    const int oz0 = 4 * vz, oy0 = 4 * vy, ox0 = 4 * vx;
    if (!m2) {
        const float4 z = make_float4(0.f, 0.f, 0.f, 0.f);
        #pragma unroll
        for (int dz = 0; dz < 4; dz++)
            #pragma unroll
            for (int dy = 0; dy < 4; dy++) {
                const int o = ((b * 128 + oz0 + dz) * 128 + (oy0 + dy)) * 128 + ox0;
                *(float4*)&out[o] = z;
            }
        return;
    }

    #pragma unroll
    for (int qz = 0; qz < 2; qz++)
    #pragma unroll
    for (int qy = 0; qy < 2; qy++) {
        float h3[2][16];
        #pragma unroll
        for (int qx = 0; qx < 2; qx++) {
            const int base = (((1 - qz) * 2 + (1 - qy)) * 2 + (1 - qx)) * 64;
            #pragma unroll
            for (int c = 0; c < 16; c++) {
                float s = p.x * sWt1[base + c];
                s = fmaf(p.y, sWt1[base + 16 + c], s);
                s = fmaf(p.z, sWt1[base + 32 + c], s);
                s = fmaf(p.w, sWt1[base + 48 + c], s);
                h3[qx][c] = fmaxf(s, 0.f);
            }
        }
        #pragma unroll
        for (int ez = 0; ez < 2; ez++)
        #pragma unroll
        for (int ey = 0; ey < 2; ey++) {
            const int kz2 = 1 - ez, ky2 = 1 - ey;
            float4 r;
            float* rp = &r.x;
            #pragma unroll
            for (int j = 0; j < 4; j++) {
                const int qx = j >> 1, ex = j & 1;
                const float* w = &sWt2[((kz2 * 2 + ky2) * 2 + (1 - ex)) * 16];
                float s = 0.f;
                #pragma unroll
                for (int c = 0; c < 16; c++) s = fmaf(h3[qx][c], w[c], s);
                rp[j] = 1.f / (1.f + __expf(-s));
            }
            const int oz = oz0 + 2 * qz + ez;
            const int oy = oy0 + 2 * qy + ey;
            const int o = ((b * 128 + oz) * 128 + oy) * 128 + ox0;
            *(float4*)&out[o] = r;
        }
    }
}

// ===========================================================================
extern "C" void kernel_launch(void* const* d_in, const int* in_sizes, int n_in,
                              void* d_out, int out_size)
{
    const float* x   = (const float*)d_in[0];
    const float* W1  = (const float*)d_in[1];
    const float* W2  = (const float*)d_in[2];
    const float* Wt1 = (const float*)d_in[3];
    const float* Wt2 = (const float*)d_in[4];
    const int*   occ = (const int*)d_in[5];
    float* out = (float*)d_out;

    k0_xm       <<<16384, 256>>>(x, occ);       // 2*128^3 threads
    k1_conv_pool<<<65536, 256>>>(occ, W1);      // 2*64^3 warps
    k2_conv     <<<65536, 256>>>(W2);           // 2*64^3 warps
    k3_tconv    <<<256,   256>>>(Wt1, Wt2, out);// 2*32^3 threads
}

// round 8
// speedup vs baseline: 1.6003x; 1.4605x over previous
#include <cuda_runtime.h>

// ---------------------------------------------------------------------------
// ConvAutoencoder round 5 = round 4 + K1 store fix (no cross-channel shfl).
//   K0: xm = x*(occ==0) -> padded (z,y:+1, x:+4) buffer, float4 stores
//   K1: conv3(1->16)+relu+mask+pool. Warp = 4 pooled voxels (32 children),
//       lane = child computing all 16 ch; weights via uniform LDS broadcast.
//       Pool via xor16/8/1 butterflies; lanes 0,2,4,6 store voxels directly.
//   K2: conv3(16->4)+relu+mask. Warp = 64-voxel x-row; weights in registers;
//       inputs as 10-reg rows per (kz,ky); shfl-reduce over 16 ci lanes.
//   K3: pool + tconv(4->16)+relu+mask + tconv(16->1)+sigmoid+mask;
//       4 threads per 32^3 voxel (one (qz,qy) quadrant each).
// conv_transpose (VALID, stride 2, k=2): out[2i+d] = W[1-d]*in[i] per dim.
// ---------------------------------------------------------------------------

#define FULLMASK 0xffffffffu
#define ZP 130
#define YP 130
#define XW 136            // 128 + 4 + 4 (keeps rows 16B aligned)
#define HP 66             // 64 + 1 + 1

// Zero-initialized device globals; halo regions never written -> stay 0.
__device__ float         g_xm  [2 * ZP * YP * XW];       // padded xm
__device__ float         g_h1pp[2 * HP * HP * HP * 16];  // padded h1 (NDHWC16)
__device__ unsigned char g_m1  [2 * 64 * 64 * 64];       // pooled mask
__device__ float         g_c2  [2 * 64 * 64 * 64 * 4];   // relu(conv2)*m1

// ===========================================================================
__global__ void __launch_bounds__(256) k0_xm(
    const float4* __restrict__ x4, const int4* __restrict__ occ4)
{
    const int i = blockIdx.x * 256 + threadIdx.x;        // 1048576 float4s
    const int xq = i & 31, yy = (i >> 5) & 127, zz = (i >> 12) & 127, b = i >> 19;
    float4 v = x4[i];
    const int4 o = occ4[i];
    v.x = (o.x == 0) ? v.x : 0.f;
    v.y = (o.y == 0) ? v.y : 0.f;
    v.z = (o.z == 0) ? v.z : 0.f;
    v.w = (o.w == 0) ? v.w : 0.f;
    ((float4*)g_xm)[((b * ZP + zz + 1) * YP + yy + 1) * (XW / 4) + xq + 1] = v;
}

// ===========================================================================
// K1: warp = 4 x-consecutive pooled voxels. lane = cz*16 + cy*8 + cx8.
// ===========================================================================
__global__ void __launch_bounds__(256) k1_conv_pool(
    const int* __restrict__ occ, const float* __restrict__ W1)
{
    __shared__ float4 sW1[108];              // [tap][cgroup]
    __shared__ float  slab[8][160];          // per-warp 4z x 4y x 10x inputs
    if (threadIdx.x < 108) sW1[threadIdx.x] = ((const float4*)W1)[threadIdx.x];
    __syncthreads();

    const int warp = threadIdx.x >> 5, lane = threadIdx.x & 31;
    const int gid = blockIdx.x * 8 + warp;               // 131072 groups
    const int px0 = (gid & 15) * 4;
    const int py = (gid >> 4) & 63, pz = (gid >> 10) & 63, b = gid >> 16;

    const int cz = lane >> 4, cy = (lane >> 3) & 1, cx8 = lane & 7;
    const int oi = ((b * 128 + 2 * pz + cz) * 128 + 2 * py + cy) * 128 + 2 * px0 + cx8;
    const unsigned B = __ballot_sync(FULLMASK, occ[oi] == 0);

    const int h1v4 = (((b * HP + pz + 1) * HP + py + 1) * HP + px0 + 1) * 4;
    const int mi = ((b * 64 + pz) * 64 + py) * 64 + px0;

    if (B == 0u) {
        if (lane < 16) ((float4*)g_h1pp)[h1v4 + lane] = make_float4(0.f, 0.f, 0.f, 0.f);
        if (lane == 0) *(uchar4*)&g_m1[mi] = make_uchar4(0, 0, 0, 0);
        return;
    }

    {   // slab: padded z in [2pz..2pz+3], y likewise, x in [2px0+3..2px0+12]
        const int xbase = ((b * ZP + 2 * pz) * YP + 2 * py) * XW + 2 * px0 + 3;
        #pragma unroll
        for (int t = 0; t < 5; t++) {
            const int l = t * 32 + lane;
            const int r = l / 10, sx = l - r * 10;       // r = sz*4 + sy
            slab[warp][l] = g_xm[xbase + (r >> 2) * (YP * XW) + (r & 3) * XW + sx];
        }
    }
    __syncwarp();

    const int loff = cz * 40 + cy * 10 + cx8;
    float acc[16];
    #pragma unroll
    for (int c = 0; c < 16; c++) acc[c] = 0.f;

    #pragma unroll
    for (int kz = 0; kz < 3; kz++)
    #pragma unroll
    for (int ky = 0; ky < 3; ky++)
    #pragma unroll
    for (int kx = 0; kx < 3; kx++) {
        const float v = slab[warp][loff + kz * 40 + ky * 10 + kx];
        const int tap = kz * 9 + ky * 3 + kx;
        #pragma unroll
        for (int g = 0; g < 4; g++) {
            const float4 w = sW1[tap * 4 + g];           // uniform -> broadcast
            acc[4 * g + 0] = fmaf(v, w.x, acc[4 * g + 0]);
            acc[4 * g + 1] = fmaf(v, w.y, acc[4 * g + 1]);
            acc[4 * g + 2] = fmaf(v, w.z, acc[4 * g + 2]);
            acc[4 * g + 3] = fmaf(v, w.w, acc[4 * g + 3]);
        }
    }

    const float mf = ((B >> lane) & 1u) ? 1.f : 0.f;
    #pragma unroll
    for (int c = 0; c < 16; c++) {
        float a = fmaxf(acc[c], 0.f) * mf;
        a = fmaxf(a, __shfl_xor_sync(FULLMASK, a, 16));  // cz
        a = fmaxf(a, __shfl_xor_sync(FULLMASK, a, 8));   // cy
        a = fmaxf(a, __shfl_xor_sync(FULLMASK, a, 1));   // cx within pair
        acc[c] = a;
    }
    // FIX: lanes 0,2,4,6 (pooled voxels 0..3) store their own 4 float4s —
    // no cross-lane register indexing, no shfl in divergent code.
    if ((lane & 1) == 0 && lane < 8) {
        const int v = lane >> 1;
        #pragma unroll
        for (int cg = 0; cg < 4; cg++) {
            float4 o;
            o.x = acc[4 * cg + 0]; o.y = acc[4 * cg + 1];
            o.z = acc[4 * cg + 2]; o.w = acc[4 * cg + 3];
            ((float4*)g_h1pp)[h1v4 + v * 4 + cg] = o;
        }
    }
    if (lane == 0) {
        uchar4 m;
        m.x = (B & (0x03030303u << 0)) ? 1 : 0;
        m.y = (B & (0x03030303u << 2)) ? 1 : 0;
        m.z = (B & (0x03030303u << 4)) ? 1 : 0;
        m.w = (B & (0x03030303u << 6)) ? 1 : 0;
        *(uchar4*)&g_m1[mi] = m;
    }
}

// ===========================================================================
// K2: warp = one 64-voxel x-row. lane = cop*16 + ci. Weights: 54 registers
// per lane (co pair 2*cop,2*cop+1 for input channel ci, all 27 taps).
// ===========================================================================
__global__ void __launch_bounds__(256) k2_conv(const float* __restrict__ W2)
{
    const int warp = threadIdx.x >> 5, lane = threadIdx.x & 31;
    const int wid = blockIdx.x * 8 + warp;               // 8192 rows
    const int vy = wid & 63, vz = (wid >> 6) & 63, b = wid >> 12;
    const int ci = lane & 15, cop = lane >> 4;

    float2 w[27];                                        // [tap]
    #pragma unroll
    for (int tap = 0; tap < 27; tap++)
        w[tap] = *(const float2*)&W2[tap * 64 + ci * 4 + cop * 2];

    const int mrow = ((b * 64 + vz) * 64 + vy) * 64;
    const int hrow = (((b * HP + vz) * HP + vy) * HP) * 16 + ci;

    for (int g = 0; g < 8; g++) {
        const int vx0 = g * 8;
        const int mv = (lane < 8) ? g_m1[mrow + vx0 + lane] : 0;
        const unsigned act = __ballot_sync(FULLMASK, mv != 0);
        if (act == 0u) {
            if (lane < 8)
                ((float4*)g_c2)[mrow + vx0 + lane] = make_float4(0.f, 0.f, 0.f, 0.f);
            continue;
        }

        float a[8][2];
        #pragma unroll
        for (int v = 0; v < 8; v++) { a[v][0] = 0.f; a[v][1] = 0.f; }

        #pragma unroll
        for (int kz = 0; kz < 3; kz++)
        #pragma unroll
        for (int ky = 0; ky < 3; ky++) {
            const int base = hrow + (kz * HP + ky) * (HP * 16) + vx0 * 16;
            float row[10];
            #pragma unroll
            for (int xx = 0; xx < 10; xx++) row[xx] = g_h1pp[base + xx * 16];
            #pragma unroll
            for (int kx = 0; kx < 3; kx++) {
                const float2 wt = w[(kz * 3 + ky) * 3 + kx];
                #pragma unroll
                for (int v = 0; v < 8; v++) {
                    a[v][0] = fmaf(row[v + kx], wt.x, a[v][0]);
                    a[v][1] = fmaf(row[v + kx], wt.y, a[v][1]);
                }
            }
        }
        #pragma unroll
        for (int v = 0; v < 8; v++) {
            float s0 = a[v][0], s1 = a[v][1];
            #pragma unroll
            for (int m = 1; m <= 8; m <<= 1) {
                s0 += __shfl_xor_sync(FULLMASK, s0, m);
                s1 += __shfl_xor_sync(FULLMASK, s1, m);
            }
            if (ci == 0) {                               // lanes 0 and 16
                const float mf = (act >> v) & 1u ? 1.f : 0.f;
                float2 r;
                r.x = fmaxf(s0, 0.f) * mf;
                r.y = fmaxf(s1, 0.f) * mf;
                ((float2*)g_c2)[(mrow + vx0 + v) * 2 + cop] = r;
            }
        }
    }
}

// ===========================================================================
// K3: 4 threads per 32^3 voxel; thread handles quadrant (qz,qy).
// ===========================================================================
__global__ void __launch_bounds__(256) k3_tconv(
    const float* __restrict__ Wt1, const float* __restrict__ Wt2,
    float* __restrict__ out)
{
    __shared__ float sWt1[512];
    __shared__ float sWt2[128];
    for (int i = threadIdx.x; i < 512; i += 256) sWt1[i] = Wt1[i];
    if (threadIdx.x < 128) sWt2[threadIdx.x] = Wt2[threadIdx.x];
    __syncthreads();

    const int t = blockIdx.x * 256 + threadIdx.x;        // 2*32^3*4
    const int q = t & 3, idx = t >> 2;
    const int qz = q >> 1, qy = q & 1;
    const int vx = idx & 31, vy = (idx >> 5) & 31, vz = (idx >> 10) & 31, b = idx >> 15;

    float4 p = make_float4(0.f, 0.f, 0.f, 0.f);
    int m2 = 0;
    #pragma unroll
    for (int d = 0; d < 8; d++) {
        const int n = ((b * 64 + 2 * vz + (d >> 2)) * 64 + 2 * vy + ((d >> 1) & 1)) * 64
                      + 2 * vx + (d & 1);
        m2 |= g_m1[n];
        const float4 c = ((const float4*)g_c2)[n];
        p.x = fmaxf(p.x, c.x); p.y = fmaxf(p.y, c.y);
        p.z = fmaxf(p.z, c.z); p.w = fmaxf(p.w, c.w);
    }

    const int oz0 = 4 * vz + 2 * qz, oy0 = 4 * vy + 2 * qy, ox0 = 4 * vx;
    if (!m2) {
        const float4 z = make_float4(0.f, 0.f, 0.f, 0.f);
        #pragma unroll
        for (int dz = 0; dz < 2; dz++)
            #pragma unroll
            for (int dy = 0; dy < 2; dy++)
                *(float4*)&out[((b * 128 + oz0 + dz) * 128 + oy0 + dy) * 128 + ox0] = z;
        return;
    }

    float h3[2][16];
    #pragma unroll
    for (int qx = 0; qx < 2; qx++) {
        const int base = (((1 - qz) * 2 + (1 - qy)) * 2 + (1 - qx)) * 64;
        #pragma unroll
        for (int c = 0; c < 16; c++) {
            float s = p.x * sWt1[base + c];
            s = fmaf(p.y, sWt1[base + 16 + c], s);
            s = fmaf(p.z, sWt1[base + 32 + c], s);
            s = fmaf(p.w, sWt1[base + 48 + c], s);
            h3[qx][c] = fmaxf(s, 0.f);
        }
    }
    #pragma unroll
    for (int ez = 0; ez < 2; ez++)
    #pragma unroll
    for (int ey = 0; ey < 2; ey++) {
        const int kz2 = 1 - ez, ky2 = 1 - ey;
        float4 r;
        float* rp = &r.x;
        #pragma unroll
        for (int j = 0; j < 4; j++) {
            const int qx = j >> 1, ex = j & 1;
            const float* wp = &sWt2[((kz2 * 2 + ky2) * 2 + (1 - ex)) * 16];
            float s = 0.f;
            #pragma unroll
            for (int c = 0; c < 16; c++) s = fmaf(h3[qx][c], wp[c], s);
            rp[j] = 1.f / (1.f + __expf(-s));
        }
        *(float4*)&out[((b * 128 + oz0 + ez) * 128 + oy0 + ey) * 128 + ox0] = r;
    }
}

// ===========================================================================
extern "C" void kernel_launch(void* const* d_in, const int* in_sizes, int n_in,
                              void* d_out, int out_size)
{
    const float* x   = (const float*)d_in[0];
    const float* W1  = (const float*)d_in[1];
    const float* W2  = (const float*)d_in[2];
    const float* Wt1 = (const float*)d_in[3];
    const float* Wt2 = (const float*)d_in[4];
    const int*   occ = (const int*)d_in[5];
    float* out = (float*)d_out;

    k0_xm       <<<4096,  256>>>((const float4*)x, (const int4*)occ);
    k1_conv_pool<<<16384, 256>>>(occ, W1);
    k2_conv     <<<1024,  256>>>(W2);
    k3_tconv    <<<1024,  256>>>(Wt1, Wt2, out);
}

// round 10
// speedup vs baseline: 1.8226x; 1.1389x over previous
#include <cuda_runtime.h>

// ---------------------------------------------------------------------------
// ConvAutoencoder round 9: sparse-compacted conv1 (worklist + atomicMax pool).
//   K0 : xm = x*(occ==0) -> padded buffer; zeroes worklist counter.
//   K1a: thread per pooled voxel: m1, zero h1, append ACTIVE children (10%)
//        to worklist (warp-aggregated atomics).
//   K1b: grid-stride over worklist; thread per active child: 27-tap conv to
//        16 ch, relu, atomicMax-scatter into pooled h1 (exact fp max >=0).
//   K2 : conv3(16->4)+relu+mask, warp per 64-voxel x-row (unchanged).
//   K3 : pool+tconv(4->16)+relu+tconv(16->1)+sigmoid; quadrant from BLOCK id
//        so weight smem reads are warp-uniform (broadcast).
// conv_transpose (VALID, stride 2, k=2): out[2i+d] = W[1-d]*in[i] per dim.
// ---------------------------------------------------------------------------

#define FULLMASK 0xffffffffu
#define ZP 130
#define YP 130
#define XW 136            // 128 + 4 + 4 (16B-aligned rows)
#define HP 66             // 64 + 1 + 1

// Zero-initialized device globals; halo regions never written -> stay 0.
__device__ float         g_xm  [2 * ZP * YP * XW];       // padded xm
__device__ float         g_h1pp[2 * HP * HP * HP * 16];  // padded pooled h1
__device__ unsigned char g_m1  [2 * 64 * 64 * 64];       // pooled mask
__device__ float         g_c2  [2 * 64 * 64 * 64 * 4];   // relu(conv2)*m1
__device__ int           g_wl  [2 * 128 * 128 * 128];    // active-child list
__device__ int           g_cnt;                          // worklist count

// ===========================================================================
// K0: masked input into padded buffer; thread 0 zeroes the worklist counter.
// ===========================================================================
__global__ void __launch_bounds__(256) k0_xm(
    const float4* __restrict__ x4, const int4* __restrict__ occ4)
{
    const int i = blockIdx.x * 256 + threadIdx.x;        // 1048576 float4s
    if (i == 0) g_cnt = 0;
    const int xq = i & 31, yy = (i >> 5) & 127, zz = (i >> 12) & 127, b = i >> 19;
    float4 v = x4[i];
    const int4 o = occ4[i];
    v.x = (o.x == 0) ? v.x : 0.f;
    v.y = (o.y == 0) ? v.y : 0.f;
    v.z = (o.z == 0) ? v.z : 0.f;
    v.w = (o.w == 0) ? v.w : 0.f;
    ((float4*)g_xm)[((b * ZP + zz + 1) * YP + yy + 1) * (XW / 4) + xq + 1] = v;
}

// ===========================================================================
// K1a: thread per pooled voxel (524288). Computes m1, zeroes pooled h1,
// appends active children to worklist (8 ballot rounds, 1 atomic each).
// ===========================================================================
__global__ void __launch_bounds__(256) k1a_scan(const int* __restrict__ occ)
{
    const int idx = blockIdx.x * 256 + threadIdx.x;
    const int px = idx & 63, py = (idx >> 6) & 63, pz = (idx >> 12) & 63, b = idx >> 18;
    const int lane = threadIdx.x & 31;

    // read 8 children occ (x-pairs as int2)
    int amask = 0;           // bit d = dz*4 + dy*2 + dx
    int cidx[8];
    #pragma unroll
    for (int dz = 0; dz < 2; dz++)
    #pragma unroll
    for (int dy = 0; dy < 2; dy++) {
        const int rb = ((b * 128 + 2 * pz + dz) * 128 + 2 * py + dy) * 128 + 2 * px;
        const int2 o = *(const int2*)&occ[rb];
        const int d0 = dz * 4 + dy * 2;
        cidx[d0] = rb; cidx[d0 + 1] = rb + 1;
        if (o.x == 0) amask |= 1 << d0;
        if (o.y == 0) amask |= 1 << (d0 + 1);
    }

    g_m1[idx] = (amask != 0);

    // zero pooled h1 interior (padded layout)
    const int h1v4 = (((b * HP + pz + 1) * HP + py + 1) * HP + px + 1) * 4;
    const float4 z = make_float4(0.f, 0.f, 0.f, 0.f);
    #pragma unroll
    for (int cg = 0; cg < 4; cg++) ((float4*)g_h1pp)[h1v4 + cg] = z;

    // warp-aggregated append of active children
    #pragma unroll
    for (int d = 0; d < 8; d++) {
        const int act = (amask >> d) & 1;
        const unsigned bal = __ballot_sync(FULLMASK, act);
        if (bal == 0u) continue;
        int base;
        if (lane == 0) base = atomicAdd(&g_cnt, __popc(bal));
        base = __shfl_sync(FULLMASK, base, 0);
        if (act) g_wl[base + __popc(bal & ((1u << lane) - 1u))] = cidx[d];
    }
}

// ===========================================================================
// K1b: thread per ACTIVE child voxel (grid-stride over worklist).
// 27-tap conv 1->16, relu, atomicMax into pooled h1 (non-negative floats:
// int compare == float compare; buffer pre-zeroed = pooling identity).
// ===========================================================================
__global__ void __launch_bounds__(256) k1b_conv(const float* __restrict__ W1)
{
    const int total = g_cnt;
    const int stride = gridDim.x * 256;
    for (int i = blockIdx.x * 256 + threadIdx.x; i < total; i += stride) {
        const int v = g_wl[i];
        const int x = v & 127, y = (v >> 7) & 127, zc = (v >> 14) & 127, b = v >> 21;

        // padded xm: center (zc+1,y+1,x+4); tap offset (kz-1,ky-1,kx-1)
        const int base = ((b * ZP + zc) * YP + y) * XW + x + 3;

        float acc[16];
        #pragma unroll
        for (int c = 0; c < 16; c++) acc[c] = 0.f;

        #pragma unroll
        for (int kz = 0; kz < 3; kz++)
        #pragma unroll
        for (int ky = 0; ky < 3; ky++)
        #pragma unroll
        for (int kx = 0; kx < 3; kx++) {
            const float vi = __ldg(&g_xm[base + kz * (YP * XW) + ky * XW + kx]);
            const int tap = kz * 9 + ky * 3 + kx;
            const float4* wp = (const float4*)&W1[tap * 16]; // warp-uniform
            #pragma unroll
            for (int g = 0; g < 4; g++) {
                const float4 w = __ldg(&wp[g]);
                acc[4 * g + 0] = fmaf(vi, w.x, acc[4 * g + 0]);
                acc[4 * g + 1] = fmaf(vi, w.y, acc[4 * g + 1]);
                acc[4 * g + 2] = fmaf(vi, w.z, acc[4 * g + 2]);
                acc[4 * g + 3] = fmaf(vi, w.w, acc[4 * g + 3]);
            }
        }

        // pooled destination (padded)
        int* dst = (int*)&g_h1pp[((((b * HP + (zc >> 1) + 1) * HP + (y >> 1) + 1) * HP
                                   + (x >> 1) + 1)) * 16];
        #pragma unroll
        for (int c = 0; c < 16; c++) {
            const float r = fmaxf(acc[c], 0.f);
            if (r > 0.f) atomicMax(&dst[c], __float_as_int(r));
        }
    }
}

// ===========================================================================
// K2: warp = one 64-voxel x-row. lane = cop*16 + ci. Weights in registers.
// ===========================================================================
__global__ void __launch_bounds__(256) k2_conv(const float* __restrict__ W2)
{
    const int warp = threadIdx.x >> 5, lane = threadIdx.x & 31;
    const int wid = blockIdx.x * 8 + warp;               // 8192 rows
    const int vy = wid & 63, vz = (wid >> 6) & 63, b = wid >> 12;
    const int ci = lane & 15, cop = lane >> 4;

    float2 w[27];
    #pragma unroll
    for (int tap = 0; tap < 27; tap++)
        w[tap] = *(const float2*)&W2[tap * 64 + ci * 4 + cop * 2];

    const int mrow = ((b * 64 + vz) * 64 + vy) * 64;
    const int hrow = (((b * HP + vz) * HP + vy) * HP) * 16 + ci;

    for (int g = 0; g < 8; g++) {
        const int vx0 = g * 8;
        const int mv = (lane < 8) ? g_m1[mrow + vx0 + lane] : 0;
        const unsigned act = __ballot_sync(FULLMASK, mv != 0);
        if (act == 0u) {
            if (lane < 8)
                ((float4*)g_c2)[mrow + vx0 + lane] = make_float4(0.f, 0.f, 0.f, 0.f);
            continue;
        }

        float a[8][2];
        #pragma unroll
        for (int v = 0; v < 8; v++) { a[v][0] = 0.f; a[v][1] = 0.f; }

        #pragma unroll
        for (int kz = 0; kz < 3; kz++)
        #pragma unroll
        for (int ky = 0; ky < 3; ky++) {
            const int base = hrow + (kz * HP + ky) * (HP * 16) + vx0 * 16;
            float row[10];
            #pragma unroll
            for (int xx = 0; xx < 10; xx++) row[xx] = g_h1pp[base + xx * 16];
            #pragma unroll
            for (int kx = 0; kx < 3; kx++) {
                const float2 wt = w[(kz * 3 + ky) * 3 + kx];
                #pragma unroll
                for (int v = 0; v < 8; v++) {
                    a[v][0] = fmaf(row[v + kx], wt.x, a[v][0]);
                    a[v][1] = fmaf(row[v + kx], wt.y, a[v][1]);
                }
            }
        }
        #pragma unroll
        for (int v = 0; v < 8; v++) {
            float s0 = a[v][0], s1 = a[v][1];
            #pragma unroll
            for (int m = 1; m <= 8; m <<= 1) {
                s0 += __shfl_xor_sync(FULLMASK, s0, m);
                s1 += __shfl_xor_sync(FULLMASK, s1, m);
            }
            if (ci == 0) {
                const float mf = (act >> v) & 1u ? 1.f : 0.f;
                float2 r;
                r.x = fmaxf(s0, 0.f) * mf;
                r.y = fmaxf(s1, 0.f) * mf;
                ((float2*)g_c2)[(mrow + vx0 + v) * 2 + cop] = r;
            }
        }
    }
}

// ===========================================================================
// K3: quadrant q from BLOCK index -> warp-uniform weight reads.
// block = (q << 8) | voxelblock; thread handles quadrant q of voxel idx.
// ===========================================================================
__global__ void __launch_bounds__(256) k3_tconv(
    const float* __restrict__ Wt1, const float* __restrict__ Wt2,
    float* __restrict__ out)
{
    __shared__ float sWt1[512];
    __shared__ float sWt2[128];
    for (int i = threadIdx.x; i < 512; i += 256) sWt1[i] = Wt1[i];
    if (threadIdx.x < 128) sWt2[threadIdx.x] = Wt2[threadIdx.x];
    __syncthreads();

    const int q = blockIdx.x >> 8;                        // 0..3, warp-uniform
    const int idx = (blockIdx.x & 255) * 256 + threadIdx.x; // 0..65535
    const int qz = q >> 1, qy = q & 1;
    const int vx = idx & 31, vy = (idx >> 5) & 31, vz = (idx >> 10) & 31, b = idx >> 15;

    float4 p = make_float4(0.f, 0.f, 0.f, 0.f);
    int m2 = 0;
    #pragma unroll
    for (int d = 0; d < 8; d++) {
        const int n = ((b * 64 + 2 * vz + (d >> 2)) * 64 + 2 * vy + ((d >> 1) & 1)) * 64
                      + 2 * vx + (d & 1);
        m2 |= g_m1[n];
        const float4 c = ((const float4*)g_c2)[n];
        p.x = fmaxf(p.x, c.x); p.y = fmaxf(p.y, c.y);
        p.z = fmaxf(p.z, c.z); p.w = fmaxf(p.w, c.w);
    }

    const int oz0 = 4 * vz + 2 * qz, oy0 = 4 * vy + 2 * qy, ox0 = 4 * vx;
    if (!m2) {
        const float4 z = make_float4(0.f, 0.f, 0.f, 0.f);
        #pragma unroll
        for (int dz = 0; dz < 2; dz++)
            #pragma unroll
            for (int dy = 0; dy < 2; dy++)
                *(float4*)&out[((b * 128 + oz0 + dz) * 128 + oy0 + dy) * 128 + ox0] = z;
        return;
    }

    float h3[2][16];
    #pragma unroll
    for (int qx = 0; qx < 2; qx++) {
        const int base = (((1 - qz) * 2 + (1 - qy)) * 2 + (1 - qx)) * 64;
        #pragma unroll
        for (int c = 0; c < 16; c++) {
            float s = p.x * sWt1[base + c];
            s = fmaf(p.y, sWt1[base + 16 + c], s);
            s = fmaf(p.z, sWt1[base + 32 + c], s);
            s = fmaf(p.w, sWt1[base + 48 + c], s);
            h3[qx][c] = fmaxf(s, 0.f);
        }
    }
    #pragma unroll
    for (int ez = 0; ez < 2; ez++)
    #pragma unroll
    for (int ey = 0; ey < 2; ey++) {
        const int kz2 = 1 - ez, ky2 = 1 - ey;
        float4 r;
        float* rp = &r.x;
        #pragma unroll
        for (int j = 0; j < 4; j++) {
            const int qx = j >> 1, ex = j & 1;
            const float* wp = &sWt2[((kz2 * 2 + ky2) * 2 + (1 - ex)) * 16];
            float s = 0.f;
            #pragma unroll
            for (int c = 0; c < 16; c++) s = fmaf(h3[qx][c], wp[c], s);
            rp[j] = 1.f / (1.f + __expf(-s));
        }
        *(float4*)&out[((b * 128 + oz0 + ez) * 128 + oy0 + ey) * 128 + ox0] = r;
    }
}

// ===========================================================================
extern "C" void kernel_launch(void* const* d_in, const int* in_sizes, int n_in,
                              void* d_out, int out_size)
{
    const float* x   = (const float*)d_in[0];
    const float* W1  = (const float*)d_in[1];
    const float* W2  = (const float*)d_in[2];
    const float* Wt1 = (const float*)d_in[3];
    const float* Wt2 = (const float*)d_in[4];
    const int*   occ = (const int*)d_in[5];
    float* out = (float*)d_out;

    k0_xm   <<<4096, 256>>>((const float4*)x, (const int4*)occ);
    k1a_scan<<<2048, 256>>>(occ);
    k1b_conv<<<2048, 256>>>(W1);
    k2_conv <<<1024, 256>>>(W2);
    k3_tconv<<<1024, 256>>>(Wt1, Wt2, out);
}

// round 11
// speedup vs baseline: 1.9421x; 1.0656x over previous
#include <cuda_runtime.h>

// ---------------------------------------------------------------------------
// ConvAutoencoder round 10:
//   K0 : xm = x*(occ==0) -> padded buffer; zeroes worklist counter.
//   K1a: thread per pooled voxel: m1, zero h1, append ACTIVE children to
//        worklist; bit31 flags "sole active child of its pooled voxel".
//   K1b: grid-stride over worklist; 27-tap conv 1->16 + relu; sole child ->
//        4x STG.128, else 16x atomicMax (exact for non-negative floats).
//   K2 : conv3(16->4)+relu+mask, warp per 64-voxel x-row; weights in SMEM
//        (was registers) -> occupancy 2x.
//   K3 : pool+tconv(4->16)+relu+tconv(16->1)+sigmoid, quadrant from block id.
// conv_transpose (VALID, stride 2, k=2): out[2i+d] = W[1-d]*in[i] per dim.
// ---------------------------------------------------------------------------

#define FULLMASK 0xffffffffu
#define ZP 130
#define YP 130
#define XW 136            // 128 + 4 + 4 (16B-aligned rows)
#define HP 66             // 64 + 1 + 1

__device__ float         g_xm  [2 * ZP * YP * XW];       // padded xm
__device__ float         g_h1pp[2 * HP * HP * HP * 16];  // padded pooled h1
__device__ unsigned char g_m1  [2 * 64 * 64 * 64];       // pooled mask
__device__ float         g_c2  [2 * 64 * 64 * 64 * 4];   // relu(conv2)*m1
__device__ int           g_wl  [2 * 128 * 128 * 128];    // active-child list
__device__ int           g_cnt;                          // worklist count

// ===========================================================================
__global__ void __launch_bounds__(256) k0_xm(
    const float4* __restrict__ x4, const int4* __restrict__ occ4)
{
    const int i = blockIdx.x * 256 + threadIdx.x;        // 1048576 float4s
    if (i == 0) g_cnt = 0;
    const int xq = i & 31, yy = (i >> 5) & 127, zz = (i >> 12) & 127, b = i >> 19;
    float4 v = x4[i];
    const int4 o = occ4[i];
    v.x = (o.x == 0) ? v.x : 0.f;
    v.y = (o.y == 0) ? v.y : 0.f;
    v.z = (o.z == 0) ? v.z : 0.f;
    v.w = (o.w == 0) ? v.w : 0.f;
    ((float4*)g_xm)[((b * ZP + zz + 1) * YP + yy + 1) * (XW / 4) + xq + 1] = v;
}

// ===========================================================================
// K1a: thread per pooled voxel (524288). m1, zero h1, worklist append.
// Worklist entry: child index | (sole ? 1<<31 : 0).
// ===========================================================================
__global__ void __launch_bounds__(256) k1a_scan(const int* __restrict__ occ)
{
    const int idx = blockIdx.x * 256 + threadIdx.x;
    const int px = idx & 63, py = (idx >> 6) & 63, pz = (idx >> 12) & 63, b = idx >> 18;
    const int lane = threadIdx.x & 31;

    int amask = 0;
    int cidx[8];
    #pragma unroll
    for (int dz = 0; dz < 2; dz++)
    #pragma unroll
    for (int dy = 0; dy < 2; dy++) {
        const int rb = ((b * 128 + 2 * pz + dz) * 128 + 2 * py + dy) * 128 + 2 * px;
        const int2 o = *(const int2*)&occ[rb];
        const int d0 = dz * 4 + dy * 2;
        cidx[d0] = rb; cidx[d0 + 1] = rb + 1;
        if (o.x == 0) amask |= 1 << d0;
        if (o.y == 0) amask |= 1 << (d0 + 1);
    }

    g_m1[idx] = (amask != 0);

    const int h1v4 = (((b * HP + pz + 1) * HP + py + 1) * HP + px + 1) * 4;
    const float4 z = make_float4(0.f, 0.f, 0.f, 0.f);
    #pragma unroll
    for (int cg = 0; cg < 4; cg++) ((float4*)g_h1pp)[h1v4 + cg] = z;

    const int sole = (__popc(amask) == 1) ? (int)0x80000000 : 0;

    #pragma unroll
    for (int d = 0; d < 8; d++) {
        const int act = (amask >> d) & 1;
        const unsigned bal = __ballot_sync(FULLMASK, act);
        if (bal == 0u) continue;
        int base;
        if (lane == 0) base = atomicAdd(&g_cnt, __popc(bal));
        base = __shfl_sync(FULLMASK, base, 0);
        if (act) g_wl[base + __popc(bal & ((1u << lane) - 1u))] = cidx[d] | sole;
    }
}

// ===========================================================================
// K1b: thread per ACTIVE child voxel. Sole child -> plain float4 stores;
// multi-child -> atomicMax per channel (buffer pre-zeroed; values >= 0).
// ===========================================================================
__global__ void __launch_bounds__(256) k1b_conv(const float* __restrict__ W1)
{
    const int total = g_cnt;
    const int stride = gridDim.x * 256;
    for (int i = blockIdx.x * 256 + threadIdx.x; i < total; i += stride) {
        const int e = g_wl[i];
        const int sole = e < 0;
        const int v = e & 0x7fffffff;
        const int x = v & 127, y = (v >> 7) & 127, zc = (v >> 14) & 127, b = v >> 21;

        const int base = ((b * ZP + zc) * YP + y) * XW + x + 3;

        float acc[16];
        #pragma unroll
        for (int c = 0; c < 16; c++) acc[c] = 0.f;

        #pragma unroll
        for (int kz = 0; kz < 3; kz++)
        #pragma unroll
        for (int ky = 0; ky < 3; ky++)
        #pragma unroll
        for (int kx = 0; kx < 3; kx++) {
            const float vi = __ldg(&g_xm[base + kz * (YP * XW) + ky * XW + kx]);
            const int tap = kz * 9 + ky * 3 + kx;
            const float4* wp = (const float4*)&W1[tap * 16]; // warp-uniform
            #pragma unroll
            for (int g = 0; g < 4; g++) {
                const float4 w = __ldg(&wp[g]);
                acc[4 * g + 0] = fmaf(vi, w.x, acc[4 * g + 0]);
                acc[4 * g + 1] = fmaf(vi, w.y, acc[4 * g + 1]);
                acc[4 * g + 2] = fmaf(vi, w.z, acc[4 * g + 2]);
                acc[4 * g + 3] = fmaf(vi, w.w, acc[4 * g + 3]);
            }
        }

        float* dstf = &g_h1pp[((((b * HP + (zc >> 1) + 1) * HP + (y >> 1) + 1) * HP
                                + (x >> 1) + 1)) * 16];
        if (sole) {
            #pragma unroll
            for (int cg = 0; cg < 4; cg++) {
                float4 o;
                o.x = fmaxf(acc[4 * cg + 0], 0.f);
                o.y = fmaxf(acc[4 * cg + 1], 0.f);
                o.z = fmaxf(acc[4 * cg + 2], 0.f);
                o.w = fmaxf(acc[4 * cg + 3], 0.f);
                ((float4*)dstf)[cg] = o;
            }
        } else {
            int* dst = (int*)dstf;
            #pragma unroll
            for (int c = 0; c < 16; c++) {
                const float r = fmaxf(acc[c], 0.f);
                if (r > 0.f) atomicMax(&dst[c], __float_as_int(r));
            }
        }
    }
}

// ===========================================================================
// K2: warp = one 64-voxel x-row. lane = cop*16 + ci. Weights in SMEM
// ([tap][cop][ci] float2, conflict-free) to lift occupancy.
// ===========================================================================
__global__ void __launch_bounds__(256) k2_conv(const float* __restrict__ W2)
{
    __shared__ float2 sW2[27 * 2 * 16];
    for (int i = threadIdx.x; i < 1728; i += 256) {
        const int tap = i >> 6, r = i & 63, ci = r >> 2, co = r & 3;
        ((float*)sW2)[((tap * 2 + (co >> 1)) * 16 + ci) * 2 + (co & 1)] = W2[i];
    }
    __syncthreads();

    const int warp = threadIdx.x >> 5, lane = threadIdx.x & 31;
    const int wid = blockIdx.x * 8 + warp;               // 8192 rows
    const int vy = wid & 63, vz = (wid >> 6) & 63, b = wid >> 12;
    const int ci = lane & 15, cop = lane >> 4;
    const float2* wlane = &sW2[cop * 16 + ci];           // stride 32 per tap

    const int mrow = ((b * 64 + vz) * 64 + vy) * 64;
    const int hrow = (((b * HP + vz) * HP + vy) * HP) * 16 + ci;

    for (int g = 0; g < 8; g++) {
        const int vx0 = g * 8;
        const int mv = (lane < 8) ? g_m1[mrow + vx0 + lane] : 0;
        const unsigned act = __ballot_sync(FULLMASK, mv != 0);
        if (act == 0u) {
            if (lane < 8)
                ((float4*)g_c2)[mrow + vx0 + lane] = make_float4(0.f, 0.f, 0.f, 0.f);
            continue;
        }

        float a[8][2];
        #pragma unroll
        for (int v = 0; v < 8; v++) { a[v][0] = 0.f; a[v][1] = 0.f; }

        #pragma unroll
        for (int kz = 0; kz < 3; kz++)
        #pragma unroll
        for (int ky = 0; ky < 3; ky++) {
            const int base = hrow + (kz * HP + ky) * (HP * 16) + vx0 * 16;
            float row[10];
            #pragma unroll
            for (int xx = 0; xx < 10; xx++) row[xx] = g_h1pp[base + xx * 16];
            #pragma unroll
            for (int kx = 0; kx < 3; kx++) {
                const float2 wt = wlane[((kz * 3 + ky) * 3 + kx) * 32];
                #pragma unroll
                for (int v = 0; v < 8; v++) {
                    a[v][0] = fmaf(row[v + kx], wt.x, a[v][0]);
                    a[v][1] = fmaf(row[v + kx], wt.y, a[v][1]);
                }
            }
        }
        #pragma unroll
        for (int v = 0; v < 8; v++) {
            float s0 = a[v][0], s1 = a[v][1];
            #pragma unroll
            for (int m = 1; m <= 8; m <<= 1) {
                s0 += __shfl_xor_sync(FULLMASK, s0, m);
                s1 += __shfl_xor_sync(FULLMASK, s1, m);
            }
            if (ci == 0) {
                const float mf = (act >> v) & 1u ? 1.f : 0.f;
                float2 r;
                r.x = fmaxf(s0, 0.f) * mf;
                r.y = fmaxf(s1, 0.f) * mf;
                ((float2*)g_c2)[(mrow + vx0 + v) * 2 + cop] = r;
            }
        }
    }
}

// ===========================================================================
// K3: quadrant q from BLOCK index -> warp-uniform weight reads.
// ===========================================================================
__global__ void __launch_bounds__(256) k3_tconv(
    const float* __restrict__ Wt1, const float* __restrict__ Wt2,
    float* __restrict__ out)
{
    __shared__ float sWt1[512];
    __shared__ float sWt2[128];
    for (int i = threadIdx.x; i < 512; i += 256) sWt1[i] = Wt1[i];
    if (threadIdx.x < 128) sWt2[threadIdx.x] = Wt2[threadIdx.x];
    __syncthreads();

    const int q = blockIdx.x >> 8;                        // 0..3, warp-uniform
    const int idx = (blockIdx.x & 255) * 256 + threadIdx.x;
    const int qz = q >> 1, qy = q & 1;
    const int vx = idx & 31, vy = (idx >> 5) & 31, vz = (idx >> 10) & 31, b = idx >> 15;

    float4 p = make_float4(0.f, 0.f, 0.f, 0.f);
    int m2 = 0;
    #pragma unroll
    for (int d = 0; d < 8; d++) {
        const int n = ((b * 64 + 2 * vz + (d >> 2)) * 64 + 2 * vy + ((d >> 1) & 1)) * 64
                      + 2 * vx + (d & 1);
        m2 |= g_m1[n];
        const float4 c = ((const float4*)g_c2)[n];
        p.x = fmaxf(p.x, c.x); p.y = fmaxf(p.y, c.y);
        p.z = fmaxf(p.z, c.z); p.w = fmaxf(p.w, c.w);
    }

    const int oz0 = 4 * vz + 2 * qz, oy0 = 4 * vy + 2 * qy, ox0 = 4 * vx;
    if (!m2) {
        const float4 z = make_float4(0.f, 0.f, 0.f, 0.f);
        #pragma unroll
        for (int dz = 0; dz < 2; dz++)
            #pragma unroll
            for (int dy = 0; dy < 2; dy++)
                *(float4*)&out[((b * 128 + oz0 + dz) * 128 + oy0 + dy) * 128 + ox0] = z;
        return;
    }

    float h3[2][16];
    #pragma unroll
    for (int qx = 0; qx < 2; qx++) {
        const int base = (((1 - qz) * 2 + (1 - qy)) * 2 + (1 - qx)) * 64;
        #pragma unroll
        for (int c = 0; c < 16; c++) {
            float s = p.x * sWt1[base + c];
            s = fmaf(p.y, sWt1[base + 16 + c], s);
            s = fmaf(p.z, sWt1[base + 32 + c], s);
            s = fmaf(p.w, sWt1[base + 48 + c], s);
            h3[qx][c] = fmaxf(s, 0.f);
        }
    }
    #pragma unroll
    for (int ez = 0; ez < 2; ez++)
    #pragma unroll
    for (int ey = 0; ey < 2; ey++) {
        const int kz2 = 1 - ez, ky2 = 1 - ey;
        float4 r;
        float* rp = &r.x;
        #pragma unroll
        for (int j = 0; j < 4; j++) {
            const int qx = j >> 1, ex = j & 1;
            const float* wp = &sWt2[((kz2 * 2 + ky2) * 2 + (1 - ex)) * 16];
            float s = 0.f;
            #pragma unroll
            for (int c = 0; c < 16; c++) s = fmaf(h3[qx][c], wp[c], s);
            rp[j] = 1.f / (1.f + __expf(-s));
        }
        *(float4*)&out[((b * 128 + oz0 + ez) * 128 + oy0 + ey) * 128 + ox0] = r;
    }
}

// ===========================================================================
extern "C" void kernel_launch(void* const* d_in, const int* in_sizes, int n_in,
                              void* d_out, int out_size)
{
    const float* x   = (const float*)d_in[0];
    const float* W1  = (const float*)d_in[1];
    const float* W2  = (const float*)d_in[2];
    const float* Wt1 = (const float*)d_in[3];
    const float* Wt2 = (const float*)d_in[4];
    const int*   occ = (const int*)d_in[5];
    float* out = (float*)d_out;

    k0_xm   <<<4096, 256>>>((const float4*)x, (const int4*)occ);
    k1a_scan<<<2048, 256>>>(occ);
    k1b_conv<<<2048, 256>>>(W1);
    k2_conv <<<1024, 256>>>(W2);
    k3_tconv<<<1024, 256>>>(Wt1, Wt2, out);
}

// round 16
// speedup vs baseline: 3.1151x; 1.6040x over previous
#include <cuda_runtime.h>

// ---------------------------------------------------------------------------
// ConvAutoencoder round 11:
//   K0 : xm = x*(occ==0) -> padded buffer; zeroes worklist counter.
//   K1a: thread per pooled voxel: m1, zero h1, block-scanned worklist append
//        (ONE atomicAdd per block; was 8 per warp -> single-address serial).
//   K1b: grid-stride over child worklist; 27-tap conv 1->16 + relu; sole
//        child -> float4 stores, else atomicMax (exact for floats >= 0).
//   K2 : conv3(16->4)+relu+mask, warp per 64-voxel x-row, smem weights;
//        joint 16-value butterfly reduction + coalesced 1-float/lane store.
//   K3 : pool+tconv(4->16)+relu+tconv(16->1)+sigmoid, quadrant from block id.
// conv_transpose (VALID, stride 2, k=2): out[2i+d] = W[1-d]*in[i] per dim.
// ---------------------------------------------------------------------------

#define FULLMASK 0xffffffffu
#define ZP 130
#define YP 130
#define XW 136            // 128 + 4 + 4 (16B-aligned rows)
#define HP 66             // 64 + 1 + 1

__device__ float         g_xm  [2 * ZP * YP * XW];       // padded xm
__device__ float         g_h1pp[2 * HP * HP * HP * 16];  // padded pooled h1
__device__ unsigned char g_m1  [2 * 64 * 64 * 64];       // pooled mask
__device__ float         g_c2  [2 * 64 * 64 * 64 * 4];   // relu(conv2)*m1
__device__ int           g_wl  [2 * 128 * 128 * 128];    // active-child list
__device__ int           g_cnt;                          // worklist count

// ===========================================================================
__global__ void __launch_bounds__(256) k0_xm(
    const float4* __restrict__ x4, const int4* __restrict__ occ4)
{
    const int i = blockIdx.x * 256 + threadIdx.x;        // 1048576 float4s
    if (i == 0) g_cnt = 0;
    const int xq = i & 31, yy = (i >> 5) & 127, zz = (i >> 12) & 127, b = i >> 19;
    float4 v = x4[i];
    const int4 o = occ4[i];
    v.x = (o.x == 0) ? v.x : 0.f;
    v.y = (o.y == 0) ? v.y : 0.f;
    v.z = (o.z == 0) ? v.z : 0.f;
    v.w = (o.w == 0) ? v.w : 0.f;
    ((float4*)g_xm)[((b * ZP + zz + 1) * YP + yy + 1) * (XW / 4) + xq + 1] = v;
}

// ===========================================================================
// K1a: thread per pooled voxel (524288). m1, zero h1, worklist append via
// block-wide exclusive scan -> ONE atomicAdd per block.
// Worklist entry: child index | (sole ? 1<<31 : 0).
// ===========================================================================
__global__ void __launch_bounds__(256) k1a_scan(const int* __restrict__ occ)
{
    const int idx = blockIdx.x * 256 + threadIdx.x;
    const int px = idx & 63, py = (idx >> 6) & 63, pz = (idx >> 12) & 63, b = idx >> 18;
    const int lane = threadIdx.x & 31, warp = threadIdx.x >> 5;

    int amask = 0;
    int cidx[8];
    #pragma unroll
    for (int dz = 0; dz < 2; dz++)
    #pragma unroll
    for (int dy = 0; dy < 2; dy++) {
        const int rb = ((b * 128 + 2 * pz + dz) * 128 + 2 * py + dy) * 128 + 2 * px;
        const int2 o = *(const int2*)&occ[rb];
        const int d0 = dz * 4 + dy * 2;
        cidx[d0] = rb; cidx[d0 + 1] = rb + 1;
        if (o.x == 0) amask |= 1 << d0;
        if (o.y == 0) amask |= 1 << (d0 + 1);
    }

    g_m1[idx] = (amask != 0);

    const int h1v4 = (((b * HP + pz + 1) * HP + py + 1) * HP + px + 1) * 4;
    const float4 z = make_float4(0.f, 0.f, 0.f, 0.f);
    #pragma unroll
    for (int cg = 0; cg < 4; cg++) ((float4*)g_h1pp)[h1v4 + cg] = z;

    const int cnt = __popc(amask);
    const int sole = (cnt == 1) ? (int)0x80000000 : 0;

    // warp inclusive scan of cnt
    int inc = cnt;
    #pragma unroll
    for (int d = 1; d < 32; d <<= 1) {
        const int n = __shfl_up_sync(FULLMASK, inc, d);
        if (lane >= d) inc += n;
    }
    __shared__ int woff[8];
    __shared__ int bbase;
    if (lane == 31) woff[warp] = inc;                    // warp totals
    __syncthreads();
    if (threadIdx.x == 0) {
        int s = 0;
        #pragma unroll
        for (int w = 0; w < 8; w++) { const int t = woff[w]; woff[w] = s; s += t; }
        bbase = atomicAdd(&g_cnt, s);                    // ONE atomic per block
    }
    __syncthreads();

    int slot = bbase + woff[warp] + (inc - cnt);
    #pragma unroll
    for (int d = 0; d < 8; d++)
        if ((amask >> d) & 1) g_wl[slot++] = cidx[d] | sole;
}

// ===========================================================================
// K1b: thread per ACTIVE child voxel. Sole child -> plain float4 stores;
// multi-child -> atomicMax per channel (buffer pre-zeroed; values >= 0).
// ===========================================================================
__global__ void __launch_bounds__(256) k1b_conv(const float* __restrict__ W1)
{
    const int total = g_cnt;
    const int stride = gridDim.x * 256;
    for (int i = blockIdx.x * 256 + threadIdx.x; i < total; i += stride) {
        const int e = g_wl[i];
        const int sole = e < 0;
        const int v = e & 0x7fffffff;
        const int x = v & 127, y = (v >> 7) & 127, zc = (v >> 14) & 127, b = v >> 21;

        const int base = ((b * ZP + zc) * YP + y) * XW + x + 3;

        float acc[16];
        #pragma unroll
        for (int c = 0; c < 16; c++) acc[c] = 0.f;

        #pragma unroll
        for (int kz = 0; kz < 3; kz++)
        #pragma unroll
        for (int ky = 0; ky < 3; ky++)
        #pragma unroll
        for (int kx = 0; kx < 3; kx++) {
            const float vi = __ldg(&g_xm[base + kz * (YP * XW) + ky * XW + kx]);
            const int tap = kz * 9 + ky * 3 + kx;
            const float4* wp = (const float4*)&W1[tap * 16]; // warp-uniform
            #pragma unroll
            for (int g = 0; g < 4; g++) {
                const float4 w = __ldg(&wp[g]);
                acc[4 * g + 0] = fmaf(vi, w.x, acc[4 * g + 0]);
                acc[4 * g + 1] = fmaf(vi, w.y, acc[4 * g + 1]);
                acc[4 * g + 2] = fmaf(vi, w.z, acc[4 * g + 2]);
                acc[4 * g + 3] = fmaf(vi, w.w, acc[4 * g + 3]);
            }
        }

        float* dstf = &g_h1pp[((((b * HP + (zc >> 1) + 1) * HP + (y >> 1) + 1) * HP
                                + (x >> 1) + 1)) * 16];
        if (sole) {
            #pragma unroll
            for (int cg = 0; cg < 4; cg++) {
                float4 o;
                o.x = fmaxf(acc[4 * cg + 0], 0.f);
                o.y = fmaxf(acc[4 * cg + 1], 0.f);
                o.z = fmaxf(acc[4 * cg + 2], 0.f);
                o.w = fmaxf(acc[4 * cg + 3], 0.f);
                ((float4*)dstf)[cg] = o;
            }
        } else {
            int* dst = (int*)dstf;
            #pragma unroll
            for (int c = 0; c < 16; c++) {
                const float r = fmaxf(acc[c], 0.f);
                if (r > 0.f) atomicMax(&dst[c], __float_as_int(r));
            }
        }
    }
}

// ===========================================================================
// K2: warp = one 64-voxel x-row. lane = cop*16 + ci. SMEM weights.
// Joint reduction: 16 partial sums (8 voxels x 2 co) reduced over the 16
// ci-lanes with a value-splitting butterfly (15 shfl); lane l ends with
// sum k=l -> one coalesced float store per lane.
// ===========================================================================
__global__ void __launch_bounds__(256) k2_conv(const float* __restrict__ W2)
{
    __shared__ float2 sW2[27 * 2 * 16];
    for (int i = threadIdx.x; i < 1728; i += 256) {
        const int tap = i >> 6, r = i & 63, ci = r >> 2, co = r & 3;
        ((float*)sW2)[((tap * 2 + (co >> 1)) * 16 + ci) * 2 + (co & 1)] = W2[i];
    }
    __syncthreads();

    const int warp = threadIdx.x >> 5, lane = threadIdx.x & 31;
    const int wid = blockIdx.x * 8 + warp;               // 8192 rows
    const int vy = wid & 63, vz = (wid >> 6) & 63, b = wid >> 12;
    const int ci = lane & 15, cop = lane >> 4;
    const float2* wlane = &sW2[cop * 16 + ci];           // stride 32 per tap

    const int mrow = ((b * 64 + vz) * 64 + vy) * 64;
    const int hrow = (((b * HP + vz) * HP + vy) * HP) * 16 + ci;

    for (int g = 0; g < 8; g++) {
        const int vx0 = g * 8;
        const int mv = (lane < 8) ? g_m1[mrow + vx0 + lane] : 0;
        const unsigned act = __ballot_sync(FULLMASK, mv != 0);
        if (act == 0u) {
            if (lane < 8)
                ((float4*)g_c2)[mrow + vx0 + lane] = make_float4(0.f, 0.f, 0.f, 0.f);
            continue;
        }

        float cur[16];                                   // k = v*2 + j
        #pragma unroll
        for (int k = 0; k < 16; k++) cur[k] = 0.f;

        #pragma unroll
        for (int kz = 0; kz < 3; kz++)
        #pragma unroll
        for (int ky = 0; ky < 3; ky++) {
            const int base = hrow + (kz * HP + ky) * (HP * 16) + vx0 * 16;
            float row[10];
            #pragma unroll
            for (int xx = 0; xx < 10; xx++) row[xx] = g_h1pp[base + xx * 16];
            #pragma unroll
            for (int kx = 0; kx < 3; kx++) {
                const float2 wt = wlane[((kz * 3 + ky) * 3 + kx) * 32];
                #pragma unroll
                for (int v = 0; v < 8; v++) {
                    cur[2 * v]     = fmaf(row[v + kx], wt.x, cur[2 * v]);
                    cur[2 * v + 1] = fmaf(row[v + kx], wt.y, cur[2 * v + 1]);
                }
            }
        }

        // joint butterfly over ci lanes: after steps d=8,4,2,1 lane l of each
        // 16-lane half holds the full sum for k = (l & 15).
        #pragma unroll
        for (int d = 8; d >= 1; d >>= 1) {
            #pragma unroll
            for (int k = 0; k < 16; k++) {               // only k < d live
                if (k < d) {
                    const float send = (lane & d) ? cur[k] : cur[k + d];
                    const float keep = (lane & d) ? cur[k + d] : cur[k];
                    cur[k] = keep + __shfl_xor_sync(FULLMASK, send, d);
                }
            }
        }

        const int k = lane & 15, v = k >> 1, j = k & 1;
        const float mf = ((act >> v) & 1u) ? 1.f : 0.f;
        g_c2[(mrow + vx0 + v) * 4 + cop * 2 + j] = fmaxf(cur[0], 0.f) * mf;
    }
}

// ===========================================================================
// K3: quadrant q from BLOCK index -> warp-uniform weight reads.
// ===========================================================================
__global__ void __launch_bounds__(256) k3_tconv(
    const float* __restrict__ Wt1, const float* __restrict__ Wt2,
    float* __restrict__ out)
{
    __shared__ float sWt1[512];
    __shared__ float sWt2[128];
    for (int i = threadIdx.x; i < 512; i += 256) sWt1[i] = Wt1[i];
    if (threadIdx.x < 128) sWt2[threadIdx.x] = Wt2[threadIdx.x];
    __syncthreads();

    const int q = blockIdx.x >> 8;                        // 0..3, warp-uniform
    const int idx = (blockIdx.x & 255) * 256 + threadIdx.x;
    const int qz = q >> 1, qy = q & 1;
    const int vx = idx & 31, vy = (idx >> 5) & 31, vz = (idx >> 10) & 31, b = idx >> 15;

    float4 p = make_float4(0.f, 0.f, 0.f, 0.f);
    int m2 = 0;
    #pragma unroll
    for (int d = 0; d < 8; d++) {
        const int n = ((b * 64 + 2 * vz + (d >> 2)) * 64 + 2 * vy + ((d >> 1) & 1)) * 64
                      + 2 * vx + (d & 1);
        m2 |= g_m1[n];
        const float4 c = ((const float4*)g_c2)[n];
        p.x = fmaxf(p.x, c.x); p.y = fmaxf(p.y, c.y);
        p.z = fmaxf(p.z, c.z); p.w = fmaxf(p.w, c.w);
    }

    const int oz0 = 4 * vz + 2 * qz, oy0 = 4 * vy + 2 * qy, ox0 = 4 * vx;
    if (!m2) {
        const float4 z = make_float4(0.f, 0.f, 0.f, 0.f);
        #pragma unroll
        for (int dz = 0; dz < 2; dz++)
            #pragma unroll
            for (int dy = 0; dy < 2; dy++)
                *(float4*)&out[((b * 128 + oz0 + dz) * 128 + oy0 + dy) * 128 + ox0] = z;
        return;
    }

    float h3[2][16];
    #pragma unroll
    for (int qx = 0; qx < 2; qx++) {
        const int base = (((1 - qz) * 2 + (1 - qy)) * 2 + (1 - qx)) * 64;
        #pragma unroll
        for (int c = 0; c < 16; c++) {
            float s = p.x * sWt1[base + c];
            s = fmaf(p.y, sWt1[base + 16 + c], s);
            s = fmaf(p.z, sWt1[base + 32 + c], s);
            s = fmaf(p.w, sWt1[base + 48 + c], s);
            h3[qx][c] = fmaxf(s, 0.f);
        }
    }
    #pragma unroll
    for (int ez = 0; ez < 2; ez++)
    #pragma unroll
    for (int ey = 0; ey < 2; ey++) {
        const int kz2 = 1 - ez, ky2 = 1 - ey;
        float4 r;
        float* rp = &r.x;
        #pragma unroll
        for (int j = 0; j < 4; j++) {
            const int qx = j >> 1, ex = j & 1;
            const float* wp = &sWt2[((kz2 * 2 + ky2) * 2 + (1 - ex)) * 16];
            float s = 0.f;
            #pragma unroll
            for (int c = 0; c < 16; c++) s = fmaf(h3[qx][c], wp[c], s);
            rp[j] = 1.f / (1.f + __expf(-s));
        }
        *(float4*)&out[((b * 128 + oz0 + ez) * 128 + oy0 + ey) * 128 + ox0] = r;
    }
}

// ===========================================================================
extern "C" void kernel_launch(void* const* d_in, const int* in_sizes, int n_in,
                              void* d_out, int out_size)
{
    const float* x   = (const float*)d_in[0];
    const float* W1  = (const float*)d_in[1];
    const float* W2  = (const float*)d_in[2];
    const float* Wt1 = (const float*)d_in[3];
    const float* Wt2 = (const float*)d_in[4];
    const int*   occ = (const int*)d_in[5];
    float* out = (float*)d_out;

    k0_xm   <<<4096, 256>>>((const float4*)x, (const int4*)occ);
    k1a_scan<<<2048, 256>>>(occ);
    k1b_conv<<<2048, 256>>>(W1);
    k2_conv <<<1024, 256>>>(W2);
    k3_tconv<<<1024, 256>>>(Wt1, Wt2, out);
}

// round 17
// speedup vs baseline: 3.2613x; 1.0469x over previous
#include <cuda_runtime.h>

// ---------------------------------------------------------------------------
// ConvAutoencoder round 16: K2 rewritten with packed fp32x2 FMA + full-width
// loads. K0/K1a/K1b/K3 identical to the 142us round-11 kernel.
//   K2: warp = 64-voxel x-row, 8 groups of 8. lane = xh*16+ci. Each half
//       loads a distinct 5-voxel sub-row (full 128B LDGs), one shfl.xor16
//       exchanges the boundary, each half computes 4 voxels x 4 co with
//       fma.rn.f32x2 (acc co-pairs packed), butterfly-reduce over ci lanes,
//       coalesced 1-float/lane store.
// conv_transpose (VALID, stride 2, k=2): out[2i+d] = W[1-d]*in[i] per dim.
// ---------------------------------------------------------------------------

#define FULLMASK 0xffffffffu
#define ZP 130
#define YP 130
#define XW 136            // 128 + 4 + 4 (16B-aligned rows)
#define HP 66             // 64 + 1 + 1

typedef unsigned long long u64;

#define PACK2(out, a, b) \
    asm("mov.b64 %0, {%1, %2};" : "=l"(out) : "r"(__float_as_uint(a)), "r"(__float_as_uint(b)))
#define UNPACK2(a, b, in) \
    do { unsigned _lo, _hi; \
         asm("mov.b64 {%0, %1}, %2;" : "=r"(_lo), "=r"(_hi) : "l"(in)); \
         a = __uint_as_float(_lo); b = __uint_as_float(_hi); } while (0)
#define FMA2(d, a, b, c) \
    asm("fma.rn.f32x2 %0, %1, %2, %3;" : "=l"(d) : "l"(a), "l"(b), "l"(c))

__device__ float         g_xm  [2 * ZP * YP * XW];       // padded xm
__device__ float         g_h1pp[2 * HP * HP * HP * 16];  // padded pooled h1
__device__ unsigned char g_m1  [2 * 64 * 64 * 64];       // pooled mask
__device__ float         g_c2  [2 * 64 * 64 * 64 * 4];   // relu(conv2)*m1
__device__ int           g_wl  [2 * 128 * 128 * 128];    // active-child list
__device__ int           g_cnt;                          // worklist count

// ===========================================================================
__global__ void __launch_bounds__(256) k0_xm(
    const float4* __restrict__ x4, const int4* __restrict__ occ4)
{
    const int i = blockIdx.x * 256 + threadIdx.x;        // 1048576 float4s
    if (i == 0) g_cnt = 0;
    const int xq = i & 31, yy = (i >> 5) & 127, zz = (i >> 12) & 127, b = i >> 19;
    float4 v = x4[i];
    const int4 o = occ4[i];
    v.x = (o.x == 0) ? v.x : 0.f;
    v.y = (o.y == 0) ? v.y : 0.f;
    v.z = (o.z == 0) ? v.z : 0.f;
    v.w = (o.w == 0) ? v.w : 0.f;
    ((float4*)g_xm)[((b * ZP + zz + 1) * YP + yy + 1) * (XW / 4) + xq + 1] = v;
}

// ===========================================================================
// K1a: thread per pooled voxel; block-scanned worklist append (1 atomic/blk).
// ===========================================================================
__global__ void __launch_bounds__(256) k1a_scan(const int* __restrict__ occ)
{
    const int idx = blockIdx.x * 256 + threadIdx.x;
    const int px = idx & 63, py = (idx >> 6) & 63, pz = (idx >> 12) & 63, b = idx >> 18;
    const int lane = threadIdx.x & 31, warp = threadIdx.x >> 5;

    int amask = 0;
    int cidx[8];
    #pragma unroll
    for (int dz = 0; dz < 2; dz++)
    #pragma unroll
    for (int dy = 0; dy < 2; dy++) {
        const int rb = ((b * 128 + 2 * pz + dz) * 128 + 2 * py + dy) * 128 + 2 * px;
        const int2 o = *(const int2*)&occ[rb];
        const int d0 = dz * 4 + dy * 2;
        cidx[d0] = rb; cidx[d0 + 1] = rb + 1;
        if (o.x == 0) amask |= 1 << d0;
        if (o.y == 0) amask |= 1 << (d0 + 1);
    }

    g_m1[idx] = (amask != 0);

    const int h1v4 = (((b * HP + pz + 1) * HP + py + 1) * HP + px + 1) * 4;
    const float4 z = make_float4(0.f, 0.f, 0.f, 0.f);
    #pragma unroll
    for (int cg = 0; cg < 4; cg++) ((float4*)g_h1pp)[h1v4 + cg] = z;

    const int cnt = __popc(amask);
    const int sole = (cnt == 1) ? (int)0x80000000 : 0;

    int inc = cnt;
    #pragma unroll
    for (int d = 1; d < 32; d <<= 1) {
        const int n = __shfl_up_sync(FULLMASK, inc, d);
        if (lane >= d) inc += n;
    }
    __shared__ int woff[8];
    __shared__ int bbase;
    if (lane == 31) woff[warp] = inc;
    __syncthreads();
    if (threadIdx.x == 0) {
        int s = 0;
        #pragma unroll
        for (int w = 0; w < 8; w++) { const int t = woff[w]; woff[w] = s; s += t; }
        bbase = atomicAdd(&g_cnt, s);
    }
    __syncthreads();

    int slot = bbase + woff[warp] + (inc - cnt);
    #pragma unroll
    for (int d = 0; d < 8; d++)
        if ((amask >> d) & 1) g_wl[slot++] = cidx[d] | sole;
}

// ===========================================================================
// K1b: thread per ACTIVE child voxel. Sole child -> float4 stores;
// multi-child -> atomicMax per channel (buffer pre-zeroed; values >= 0).
// ===========================================================================
__global__ void __launch_bounds__(256) k1b_conv(const float* __restrict__ W1)
{
    const int total = g_cnt;
    const int stride = gridDim.x * 256;
    for (int i = blockIdx.x * 256 + threadIdx.x; i < total; i += stride) {
        const int e = g_wl[i];
        const int sole = e < 0;
        const int v = e & 0x7fffffff;
        const int x = v & 127, y = (v >> 7) & 127, zc = (v >> 14) & 127, b = v >> 21;

        const int base = ((b * ZP + zc) * YP + y) * XW + x + 3;

        float acc[16];
        #pragma unroll
        for (int c = 0; c < 16; c++) acc[c] = 0.f;

        #pragma unroll
        for (int kz = 0; kz < 3; kz++)
        #pragma unroll
        for (int ky = 0; ky < 3; ky++)
        #pragma unroll
        for (int kx = 0; kx < 3; kx++) {
            const float vi = __ldg(&g_xm[base + kz * (YP * XW) + ky * XW + kx]);
            const int tap = kz * 9 + ky * 3 + kx;
            const float4* wp = (const float4*)&W1[tap * 16];
            #pragma unroll
            for (int g = 0; g < 4; g++) {
                const float4 w = __ldg(&wp[g]);
                acc[4 * g + 0] = fmaf(vi, w.x, acc[4 * g + 0]);
                acc[4 * g + 1] = fmaf(vi, w.y, acc[4 * g + 1]);
                acc[4 * g + 2] = fmaf(vi, w.z, acc[4 * g + 2]);
                acc[4 * g + 3] = fmaf(vi, w.w, acc[4 * g + 3]);
            }
        }

        float* dstf = &g_h1pp[((((b * HP + (zc >> 1) + 1) * HP + (y >> 1) + 1) * HP
                                + (x >> 1) + 1)) * 16];
        if (sole) {
            #pragma unroll
            for (int cg = 0; cg < 4; cg++) {
                float4 o;
                o.x = fmaxf(acc[4 * cg + 0], 0.f);
                o.y = fmaxf(acc[4 * cg + 1], 0.f);
                o.z = fmaxf(acc[4 * cg + 2], 0.f);
                o.w = fmaxf(acc[4 * cg + 3], 0.f);
                ((float4*)dstf)[cg] = o;
            }
        } else {
            int* dst = (int*)dstf;
            #pragma unroll
            for (int c = 0; c < 16; c++) {
                const float r = fmaxf(acc[c], 0.f);
                if (r > 0.f) atomicMax(&dst[c], __float_as_int(r));
            }
        }
    }
}

// ===========================================================================
// K2: warp = one 64-voxel x-row. lane = xh*16 + ci (xh = x-half).
// Half xh loads xx = 5*xh + r (r=0..4); one shfl.xor16 exchanges the
// boundary value. Each half computes its 4 voxels x 4 co with packed
// f32x2 FMA, then a 16-lane value-splitting butterfly; coalesced store.
// ===========================================================================
__global__ void __launch_bounds__(256) k2_conv(const float* __restrict__ W2)
{
    __shared__ float4 sW[27 * 16];          // [tap][ci] = 4 co weights
    for (int i = threadIdx.x; i < 432; i += 256) sW[i] = ((const float4*)W2)[i];
    __syncthreads();

    const int warp = threadIdx.x >> 5, lane = threadIdx.x & 31;
    const int wid = blockIdx.x * 8 + warp;               // 8192 rows
    const int vy = wid & 63, vz = (wid >> 6) & 63, b = wid >> 12;
    const int ci = lane & 15, xh = lane >> 4;

    const int mrow = ((b * 64 + vz) * 64 + vy) * 64;
    const int hrow = (((b * HP + vz) * HP + vy) * HP) * 16 + ci;

    for (int g = 0; g < 8; g++) {
        const int vx0 = g * 8;
        const int mv = (lane < 8) ? g_m1[mrow + vx0 + lane] : 0;
        const unsigned act = __ballot_sync(FULLMASK, mv != 0);
        if (act == 0u) {
            if (lane < 8)
                ((float4*)g_c2)[mrow + vx0 + lane] = make_float4(0.f, 0.f, 0.f, 0.f);
            continue;
        }

        u64 acc[4][2];                                   // [v_local][co-pair]
        #pragma unroll
        for (int v = 0; v < 4; v++) { acc[v][0] = 0ull; acc[v][1] = 0ull; }

        #pragma unroll
        for (int kz = 0; kz < 3; kz++)
        #pragma unroll
        for (int ky = 0; ky < 3; ky++) {
            const int base = hrow + (kz * HP + ky) * (HP * 16) + (vx0 + 5 * xh) * 16;
            float r5[5];
            #pragma unroll
            for (int r = 0; r < 5; r++) r5[r] = g_h1pp[base + r * 16];
            const float bnd = __shfl_xor_sync(FULLMASK, xh ? r5[0] : r5[4], 16);

            // L[0..5]: half0 = xx 0..5, half1 = xx 4..9
            float L[6];
            L[0] = xh ? bnd : r5[0];
            #pragma unroll
            for (int x = 1; x < 5; x++) L[x] = xh ? r5[x - 1] : r5[x];
            L[5] = xh ? r5[4] : bnd;

            u64 Ld[6];
            #pragma unroll
            for (int x = 0; x < 6; x++) PACK2(Ld[x], L[x], L[x]);

            #pragma unroll
            for (int kx = 0; kx < 3; kx++) {
                const float4 w = sW[((kz * 3 + ky) * 3 + kx) * 16 + ci];
                u64 w01, w23;
                PACK2(w01, w.x, w.y);
                PACK2(w23, w.z, w.w);
                #pragma unroll
                for (int v = 0; v < 4; v++) {
                    FMA2(acc[v][0], Ld[v + kx], w01, acc[v][0]);
                    FMA2(acc[v][1], Ld[v + kx], w23, acc[v][1]);
                }
            }
        }

        // unpack to cur[k], k = v_local*4 + co
        float cur[16];
        #pragma unroll
        for (int v = 0; v < 4; v++) {
            UNPACK2(cur[v * 4 + 0], cur[v * 4 + 1], acc[v][0]);
            UNPACK2(cur[v * 4 + 2], cur[v * 4 + 3], acc[v][1]);
        }

        // value-splitting butterfly over the 16 ci lanes of each half
        #pragma unroll
        for (int d = 8; d >= 1; d >>= 1) {
            #pragma unroll
            for (int k = 0; k < 16; k++) {
                if (k < d) {
                    const float send = (lane & d) ? cur[k] : cur[k + d];
                    const float keep = (lane & d) ? cur[k + d] : cur[k];
                    cur[k] = keep + __shfl_xor_sync(FULLMASK, send, d);
                }
            }
        }

        const int k = lane & 15;
        const int vg = xh * 4 + (k >> 2);                // voxel 0..7
        const int co = k & 3;
        const float mf = ((act >> vg) & 1u) ? 1.f : 0.f;
        g_c2[(mrow + vx0 + vg) * 4 + co] = fmaxf(cur[0], 0.f) * mf;
    }
}

// ===========================================================================
// K3: quadrant q from BLOCK index -> warp-uniform weight reads.
// ===========================================================================
__global__ void __launch_bounds__(256) k3_tconv(
    const float* __restrict__ Wt1, const float* __restrict__ Wt2,
    float* __restrict__ out)
{
    __shared__ float sWt1[512];
    __shared__ float sWt2[128];
    for (int i = threadIdx.x; i < 512; i += 256) sWt1[i] = Wt1[i];
    if (threadIdx.x < 128) sWt2[threadIdx.x] = Wt2[threadIdx.x];
    __syncthreads();

    const int q = blockIdx.x >> 8;                        // 0..3, warp-uniform
    const int idx = (blockIdx.x & 255) * 256 + threadIdx.x;
    const int qz = q >> 1, qy = q & 1;
    const int vx = idx & 31, vy = (idx >> 5) & 31, vz = (idx >> 10) & 31, b = idx >> 15;

    float4 p = make_float4(0.f, 0.f, 0.f, 0.f);
    int m2 = 0;
    #pragma unroll
    for (int d = 0; d < 8; d++) {
        const int n = ((b * 64 + 2 * vz + (d >> 2)) * 64 + 2 * vy + ((d >> 1) & 1)) * 64
                      + 2 * vx + (d & 1);
        m2 |= g_m1[n];
        const float4 c = ((const float4*)g_c2)[n];
        p.x = fmaxf(p.x, c.x); p.y = fmaxf(p.y, c.y);
        p.z = fmaxf(p.z, c.z); p.w = fmaxf(p.w, c.w);
    }

    const int oz0 = 4 * vz + 2 * qz, oy0 = 4 * vy + 2 * qy, ox0 = 4 * vx;
    if (!m2) {
        const float4 z = make_float4(0.f, 0.f, 0.f, 0.f);
        #pragma unroll
        for (int dz = 0; dz < 2; dz++)
            #pragma unroll
            for (int dy = 0; dy < 2; dy++)
                *(float4*)&out[((b * 128 + oz0 + dz) * 128 + oy0 + dy) * 128 + ox0] = z;
        return;
    }

    float h3[2][16];
    #pragma unroll
    for (int qx = 0; qx < 2; qx++) {
        const int base = (((1 - qz) * 2 + (1 - qy)) * 2 + (1 - qx)) * 64;
        #pragma unroll
        for (int c = 0; c < 16; c++) {
            float s = p.x * sWt1[base + c];
            s = fmaf(p.y, sWt1[base + 16 + c], s);
            s = fmaf(p.z, sWt1[base + 32 + c], s);
            s = fmaf(p.w, sWt1[base + 48 + c], s);
            h3[qx][c] = fmaxf(s, 0.f);
        }
    }
    #pragma unroll
    for (int ez = 0; ez < 2; ez++)
    #pragma unroll
    for (int ey = 0; ey < 2; ey++) {
        const int kz2 = 1 - ez, ky2 = 1 - ey;
        float4 r;
        float* rp = &r.x;
        #pragma unroll
        for (int j = 0; j < 4; j++) {
            const int qx = j >> 1, ex = j & 1;
            const float* wp = &sWt2[((kz2 * 2 + ky2) * 2 + (1 - ex)) * 16];
            float s = 0.f;
            #pragma unroll
            for (int c = 0; c < 16; c++) s = fmaf(h3[qx][c], wp[c], s);
            rp[j] = 1.f / (1.f + __expf(-s));
        }
        *(float4*)&out[((b * 128 + oz0 + ez) * 128 + oy0 + ey) * 128 + ox0] = r;
    }
}

// ===========================================================================
extern "C" void kernel_launch(void* const* d_in, const int* in_sizes, int n_in,
                              void* d_out, int out_size)
{
    const float* x   = (const float*)d_in[0];
    const float* W1  = (const float*)d_in[1];
    const float* W2  = (const float*)d_in[2];
    const float* Wt1 = (const float*)d_in[3];
    const float* Wt2 = (const float*)d_in[4];
    const int*   occ = (const int*)d_in[5];
    float* out = (float*)d_out;

    k0_xm   <<<4096, 256>>>((const float4*)x, (const int4*)occ);
    k1a_scan<<<2048, 256>>>(occ);
    k1b_conv<<<2048, 256>>>(W1);
    k2_conv <<<1024, 256>>>(W2);
    k3_tconv<<<1024, 256>>>(Wt1, Wt2, out);
}